// round 13
// baseline (speedup 1.0000x reference)
#include <cuda_runtime.h>

#define Bq 8
#define Nn 1024
#define Mw 64
#define Ee 63456
#define NROWS (Bq*Nn)          /* 8192 node rows */
#define NTASK (Bq*Nn)

#define GRID    152
#define NSTREAM (GRID*2)       /* 304 task streams */

typedef unsigned long long ull;

// ---------------- device scratch ----------------
__device__ float g_Wcat[64*192];        // edge-side:  [We_edge | Wn_edge | W_e_edge]
__device__ float g_WcatP[64*192];       // node-side:  [We_src  | Wn_src  | Wn_dst ]
__device__ float g_be[64];
__device__ float g_bn[64];
__device__ float g_P[NROWS*192];        // node projections [Pes | Pns | Pnd]
__device__ float g_agg[NROWS*64];       // agg_n

__device__ __forceinline__ int node_w(int i)      { return i < Mw ? i : Mw; }
__device__ __forceinline__ int node_start(int i)  { return i <= Mw ? (i*(i-1))/2 : 2016 + (i-Mw)*Mw; }

// ---------------- packed fp32x2 helpers ----------------
__device__ __forceinline__ void fma2(ull &d, ull a, ull b) {
    asm("fma.rn.f32x2 %0, %1, %2, %0;" : "+l"(d) : "l"(a), "l"(b));
}
__device__ __forceinline__ ull bcast2(float x) {
    ull r; asm("mov.b64 %0, {%1, %1};" : "=l"(r) : "f"(x)); return r;
}
__device__ __forceinline__ float2 unpk(ull v) {
    float2 r; asm("mov.b64 {%0, %1}, %2;" : "=f"(r.x), "=f"(r.y) : "l"(v)); return r;
}
__device__ __forceinline__ ull pk(float x, float y) {
    ull r; asm("mov.b64 %0, {%1, %2};" : "=l"(r) : "f"(x), "f"(y)); return r;
}
__device__ __forceinline__ void gbar(int id) {
    asm volatile("bar.sync %0, %1;" :: "r"(id), "r"(256) : "memory");
}
// pinned-placement vector load (volatile: ptxas cannot sink it)
__device__ __forceinline__ float2 ldg2v(const float* p) {
    float2 v;
    asm volatile("ld.global.nc.v2.f32 {%0, %1}, [%2];" : "=f"(v.x), "=f"(v.y) : "l"(p));
    return v;
}

// ---------------- shared layout (floats); tile stride 68 (16B-aligned rows) ----------------
#define STRD     68
#define SZ_AT    (64*STRD)     /* 4352 */
#define OFF_W1   0             /* 12288 */
#define OFF_W2   12288         /* 4096  */
#define OFF_BE   16384
#define OFF_BN   16448
#define OFF_BO   16512
#define OFF_RCP  16576
#define OFF_AT   16640         /* [2 grp][2 buf][4352] = 17408 */
#define OFF_PET  34048         /* [2 grp][4352] = 8704 */
#define OFF_SRED 42752         /* [2 grp][2 par][512] = 2048 */
#define OFF_SWR  44800         /* [2 grp][2 par][256 ull] = 2048 floats */
#define SMEM_FLOATS 46848
#define SMEM_BYTES  (SMEM_FLOATS*4)

// ---------------- K0: build fused weight blocks directly (ILP-4 dot products) ----------------
__global__ void k_prep(const float* __restrict__ We1, const float* __restrict__ We2,
                       const float* __restrict__ be1, const float* __restrict__ be2,
                       const float* __restrict__ Wn1, const float* __restrict__ bn1,
                       const float* __restrict__ Wn2, const float* __restrict__ bn2,
                       const float* __restrict__ W_edges) {
    int idx = blockIdx.x*blockDim.x + threadIdx.x;
    if (idx < 64*192) {
        int j = idx / 192, c = idx % 192;
        float v;
        if (c < 64) {
            float s0=0.f,s1=0.f,s2=0.f,s3=0.f;
            const float* a = We1 + (64+j)*128;
            for (int t = 0; t < 128; t += 4) {
                s0 += a[t+0]*We2[(t+0)*64+c]; s1 += a[t+1]*We2[(t+1)*64+c];
                s2 += a[t+2]*We2[(t+2)*64+c]; s3 += a[t+3]*We2[(t+3)*64+c];
            }
            v = (s0+s1)+(s2+s3);
        } else if (c < 128) {
            int cc = c - 64;
            float s0=0.f,s1=0.f,s2=0.f,s3=0.f;
            const float* a = Wn1 + (128+j)*128;
            for (int t = 0; t < 128; t += 4) {
                s0 += a[t+0]*Wn2[(t+0)*64+cc]; s1 += a[t+1]*Wn2[(t+1)*64+cc];
                s2 += a[t+2]*Wn2[(t+2)*64+cc]; s3 += a[t+3]*Wn2[(t+3)*64+cc];
            }
            v = (s0+s1)+(s2+s3);
        } else {
            v = W_edges[(64+j)*64 + (c-128)];
        }
        g_Wcat[idx] = v;
        return;
    }
    int i2 = idx - 64*192;
    if (i2 >= 0 && i2 < 64*192) {
        int j = i2 / 192, c = i2 % 192;
        const float* a; const float* B; int cc;
        if (c < 64)       { a = We1 + j*128;      B = We2; cc = c; }
        else if (c < 128) { a = Wn1 + j*128;      B = Wn2; cc = c - 64; }
        else              { a = Wn1 + (64+j)*128; B = Wn2; cc = c - 128; }
        float s0=0.f,s1=0.f,s2=0.f,s3=0.f;
        for (int t = 0; t < 128; t += 4) {
            s0 += a[t+0]*B[(t+0)*64+cc]; s1 += a[t+1]*B[(t+1)*64+cc];
            s2 += a[t+2]*B[(t+2)*64+cc]; s3 += a[t+3]*B[(t+3)*64+cc];
        }
        g_WcatP[i2] = (s0+s1)+(s2+s3);
        return;
    }
    int i3 = idx - 2*64*192;
    if (i3 >= 0 && i3 < 64) {
        float s = be2[i3];
        for (int t = 0; t < 128; t++) s += be1[t]*We2[t*64+i3];
        g_be[i3] = s;
    } else if (i3 >= 64 && i3 < 128) {
        int c = i3 - 64; float s = bn2[c];
        for (int t = 0; t < 128; t++) s += bn1[t]*Wn2[t*64+c];
        g_bn[c] = s;
    }
}

// ---------------- K1: node projections GEMM; 512 blocks x 16-row tiles ----------------
__global__ void __launch_bounds__(256,2) k_nodeproj(const float* __restrict__ A) {
    __shared__ float sW[64*192];
    __shared__ float sA[16][68];
    for (int idx = threadIdx.x; idx < 64*192; idx += 256) sW[idx] = g_WcatP[idx];
    int tx = threadIdx.x & 31, ty = threadIdx.x >> 5;
    int tile = blockIdx.x;                 // 512 tiles of 16 rows
    if (threadIdx.x < 16*16) {
        const float4* src = (const float4*)(A + (size_t)tile*16*64);
        int r = threadIdx.x >> 4, q = threadIdx.x & 15;
        ((float4*)&sA[r][0])[q] = src[threadIdx.x];
    }
    __syncthreads();
    float acc[2][6];
    #pragma unroll
    for (int a = 0; a < 2; a++)
        #pragma unroll
        for (int b = 0; b < 6; b++) acc[a][b] = 0.f;
    for (int j = 0; j < 64; j += 4) {
        float4 av[2];
        #pragma unroll
        for (int ri = 0; ri < 2; ri++) av[ri] = *(const float4*)&sA[ty*2 + ri][j];
        #pragma unroll
        for (int jj = 0; jj < 4; jj++) {
            float wv[6];
            #pragma unroll
            for (int ci = 0; ci < 6; ci++) wv[ci] = sW[(j+jj)*192 + tx + 32*ci];
            #pragma unroll
            for (int ri = 0; ri < 2; ri++) {
                float a = (jj==0) ? av[ri].x : (jj==1) ? av[ri].y : (jj==2) ? av[ri].z : av[ri].w;
                #pragma unroll
                for (int ci = 0; ci < 6; ci++) acc[ri][ci] += a * wv[ci];
            }
        }
    }
    float* dst = g_P + (size_t)tile*16*192;
    #pragma unroll
    for (int ri = 0; ri < 2; ri++) {
        int r = ty*2 + ri;
        #pragma unroll
        for (int ci = 0; ci < 6; ci++)
            dst[(size_t)r*192 + tx + 32*ci] = acc[ri][ci];
    }
}

// ---------------- K2: fused pipeline (R12 + early barrier, reordered tail) ----------------
__global__ void __launch_bounds__(512,1) k_fusededge(const float* __restrict__ edges,
                                                     const float* __restrict__ W_edges,
                                                     const float* __restrict__ bias,
                                                     float* __restrict__ out_edges) {
    extern __shared__ float sm[];
    float* sW1  = sm + OFF_W1;
    float* sW2  = sm + OFF_W2;
    float* sbe  = sm + OFF_BE;
    float* sbn  = sm + OFF_BN;
    float* sbo  = sm + OFF_BO;
    float* srcp = sm + OFF_RCP;
    int tid = threadIdx.x;

    for (int idx = tid; idx < 64*192; idx += 512) sW1[idx] = g_Wcat[idx];
    for (int idx = tid; idx < 64*64;  idx += 512) sW2[idx] = W_edges[idx];
    if (tid < 64) {
        sbe[tid] = g_be[tid];
        sbn[tid] = g_bn[tid];
        sbo[tid] = bias[tid];
        srcp[tid] = 1.0f / (float)(tid > 0 ? tid : 1);
    }
    __syncthreads();

    int grp  = tid >> 8;            // warp-group 0/1
    int gtid = tid & 255;
    int tx = gtid & 31, ty = gtid >> 5;
    int bar = grp + 1;
    int r0t = 8*ty;                 // this warp's first row
    int c0 = 2*tx;                  // this thread's first col per 64-segment

    float* sPeT  = sm + OFF_PET  + grp*SZ_AT;
    float* bufA  = sm + OFF_AT + (grp*2+0)*SZ_AT;
    float* bufB  = sm + OFF_AT + (grp*2+1)*SZ_AT;
    float* sredB = sm + OFF_SRED + grp*1024;
    ull*   swrB  = (ull*)(sm + OFF_SWR) + grp*512;

    int task = blockIdx.x*2 + grp;

    // ---- prologue: own-warp rows of first tile ----
    {
        int b = task >> 10, i = task & 1023;
        size_t ebase = (size_t)b*Ee + node_start(i);
        const float4* src = (const float4*)(edges + ebase*64);
        #pragma unroll
        for (int k = 0; k < 4; k++) {
            int idx = tx + 32*k;
            int rl = idx >> 4, q = idx & 15;
            float4 v = __ldg(src + (r0t + rl)*16 + q);
            int j = 4*q, r = r0t + rl;
            bufA[(j+0)*STRD + r] = v.x; bufA[(j+1)*STRD + r] = v.y;
            bufA[(j+2)*STRD + r] = v.z; bufA[(j+3)*STRD + r] = v.w;
        }
    }
    __syncwarp();

    // ---- de-phase the two warp-groups by ~half a task-round (verified +1.8us) ----
    if (grp == 1) {
        long long t0 = clock64();
        while (clock64() - t0 < 8000) {}
    }

    float* curAT = bufA;
    float* nxtAT = bufB;
    int par = 0;

    for (; task < NTASK; task += NSTREAM, par ^= 1) {
        int b = task >> 10, i = task & 1023;
        int w = node_w(i), ns = node_start(i);
        size_t ebase = (size_t)b*Ee + ns;
        int srow0 = (b << 10) + (i - w);
        int ntask = task + NSTREAM;
        bool hasn = ntask < NTASK;
        float* sredW = sredB + par*512;
        ull*   swrW  = swrB + par*256;

        // ---- GEMM1 part A: j = 0..47 ----
        ull acc[4][6];
        #pragma unroll
        for (int q = 0; q < 4; q++)
            #pragma unroll
            for (int c2 = 0; c2 < 6; c2++) acc[q][c2] = 0ull;
        #pragma unroll 8
        for (int j = 0; j < 48; j++) {
            ulonglong2 aA = *(const ulonglong2*)&curAT[j*STRD + r0t];
            ulonglong2 aB = *(const ulonglong2*)&curAT[j*STRD + r0t + 4];
            ull a2[4] = {aA.x, aA.y, aB.x, aB.y};
            #pragma unroll
            for (int g = 0; g < 3; g++) {
                float2 wp = *(const float2*)&sW1[j*192 + 64*g + c0];
                ull w20 = bcast2(wp.x);
                ull w21 = bcast2(wp.y);
                #pragma unroll
                for (int q = 0; q < 4; q++) {
                    fma2(acc[q][2*g+0], a2[q], w20);
                    fma2(acc[q][2*g+1], a2[q], w21);
                }
            }
        }

        // ---- issue g_P loads NOW (covered by remaining 16 j-iters) ----
        float2 pnd, pfe[8], pfn[8];
        {
            size_t pb = (size_t)task*192;
            pnd = ldg2v(&g_P[pb + 128 + c0]);
            #pragma unroll
            for (int ri = 0; ri < 8; ri++) {
                size_t sr = (size_t)(srow0 + r0t + ri)*192;
                pfe[ri] = ldg2v(&g_P[sr + c0]);
                pfn[ri] = ldg2v(&g_P[sr + 64 + c0]);
            }
        }

        // ---- GEMM1 part B: j = 48..63 ----
        #pragma unroll 8
        for (int j = 48; j < 64; j++) {
            ulonglong2 aA = *(const ulonglong2*)&curAT[j*STRD + r0t];
            ulonglong2 aB = *(const ulonglong2*)&curAT[j*STRD + r0t + 4];
            ull a2[4] = {aA.x, aA.y, aB.x, aB.y};
            #pragma unroll
            for (int g = 0; g < 3; g++) {
                float2 wp = *(const float2*)&sW1[j*192 + 64*g + c0];
                ull w20 = bcast2(wp.x);
                ull w21 = bcast2(wp.y);
                #pragma unroll
                for (int q = 0; q < 4; q++) {
                    fma2(acc[q][2*g+0], a2[q], w20);
                    fma2(acc[q][2*g+1], a2[q], w21);
                }
            }
        }

        float2 be2v = *(const float2*)&sbe[c0];
        float2 bn2v = *(const float2*)&sbn[c0];

        // ---- epilogue: ReLU; pair_e -> sPeT (warp-local rows); pair_n partials ----
        float np0 = 0.f, np1 = 0.f;
        #pragma unroll
        for (int q = 0; q < 4; q++) {
            int rA = 2*q, rB = 2*q + 1;
            int gA = (r0t + rA) < w, gB = (r0t + rB) < w;
            float2 e0 = unpk(acc[q][0]);
            float2 e1 = unpk(acc[q][1]);
            float2 n0 = unpk(acc[q][2]);
            float2 n1 = unpk(acc[q][3]);
            float p0A = e0.x + pfe[rA].x + be2v.x;
            float p0B = e0.y + pfe[rB].x + be2v.x;
            p0A = (gA && p0A > 0.f) ? p0A : 0.f;
            p0B = (gB && p0B > 0.f) ? p0B : 0.f;
            *(ull*)&sPeT[(c0+0)*STRD + r0t + rA] = pk(p0A, p0B);
            float p1A = e1.x + pfe[rA].y + be2v.y;
            float p1B = e1.y + pfe[rB].y + be2v.y;
            p1A = (gA && p1A > 0.f) ? p1A : 0.f;
            p1B = (gB && p1B > 0.f) ? p1B : 0.f;
            *(ull*)&sPeT[(c0+1)*STRD + r0t + rA] = pk(p1A, p1B);
            float q0A = n0.x + pfn[rA].x + pnd.x + bn2v.x;
            float q0B = n0.y + pfn[rB].x + pnd.x + bn2v.x;
            if (gA && q0A > 0.f) np0 += q0A;
            if (gB && q0B > 0.f) np0 += q0B;
            float q1A = n1.x + pfn[rA].y + pnd.y + bn2v.y;
            float q1B = n1.y + pfn[rB].y + pnd.y + bn2v.y;
            if (gA && q1A > 0.f) np1 += q1A;
            if (gB && q1B > 0.f) np1 += q1B;
        }
        *(ull*)&sredW[ty*64 + c0] = pk(np0, np1);

        // ---- prefetch next tile (own-warp rows; LDGs fly under GEMM2) ----
        float4 pf4[4];
        if (hasn) {
            int nb = ntask >> 10, ni = ntask & 1023;
            size_t nebase = (size_t)nb*Ee + node_start(ni);
            const float4* nsrc = (const float4*)(edges + nebase*64);
            #pragma unroll
            for (int k = 0; k < 4; k++) {
                int idx = tx + 32*k;
                pf4[k] = __ldg(nsrc + (r0t + (idx >> 4))*16 + (idx & 15));
            }
        }
        __syncwarp();                        // sPeT rows are warp-local

        // ---- GEMM2: R = pair_e @ W_mean (own sPeT rows) ----
        ull acc20[4], acc21[4];
        #pragma unroll
        for (int p = 0; p < 4; p++) { acc20[p] = 0ull; acc21[p] = 0ull; }
        #pragma unroll 8
        for (int j = 0; j < 64; j++) {
            ulonglong2 aA = *(const ulonglong2*)&sPeT[j*STRD + r0t];
            ulonglong2 aB = *(const ulonglong2*)&sPeT[j*STRD + r0t + 4];
            ull a2[4] = {aA.x, aA.y, aB.x, aB.y};
            float2 wp = *(const float2*)&sW2[j*64 + c0];
            ull w20 = bcast2(wp.x);
            ull w21 = bcast2(wp.y);
            #pragma unroll
            for (int q = 0; q < 4; q++) {
                fma2(acc20[q], a2[q], w20);
                fma2(acc21[q], a2[q], w21);
            }
        }

        // ---- exclusive row-prefix (in-register) + warp totals ----
        float s0[8], s1[8];
        #pragma unroll
        for (int q = 0; q < 4; q++) {
            float2 v0 = unpk(acc20[q]);
            float2 v1 = unpk(acc21[q]);
            s0[2*q] = v0.x; s0[2*q+1] = v0.y;
            s1[2*q] = v1.x; s1[2*q+1] = v1.y;
        }
        float ex0[8], ex1[8], run0 = 0.f, run1 = 0.f;
        #pragma unroll
        for (int ri = 0; ri < 8; ri++) {
            ex0[ri] = run0; run0 += s0[ri];
            ex1[ri] = run1; run1 += s1[ri];
        }
        swrW[ty*32 + tx] = pk(run0, run1);

        gbar(bar);            // EARLY barrier: sred/swr written; tile store is warp-local

        // ---- store prefetched tile into alternate buffer (own rows; overlaps carry lat) ----
        if (hasn) {
            #pragma unroll
            for (int k = 0; k < 4; k++) {
                int idx = tx + 32*k;
                int r = r0t + (idx >> 4), j = 4*(idx & 15);
                nxtAT[(j+0)*STRD + r] = pf4[k].x; nxtAT[(j+1)*STRD + r] = pf4[k].y;
                nxtAT[(j+2)*STRD + r] = pf4[k].z; nxtAT[(j+3)*STRD + r] = pf4[k].w;
            }
        }

        // ---- agg_n write (independent of carry) ----
        if (gtid < 64) {
            int c = gtid;
            float a = 0.f;
            #pragma unroll
            for (int t = 0; t < 8; t++) a += sredW[t*64 + c];
            g_agg[(size_t)task*64 + c] = a * (1.0f / (float)(w > 0 ? w : 1));
        }

        // ---- warp-carry (predicated, unrolled) ----
        float cc0 = 0.f, cc1 = 0.f;
        #pragma unroll
        for (int t = 0; t < 7; t++) {
            if (t < ty) {
                float2 v = unpk(swrW[t*32 + tx]);
                cc0 += v.x; cc1 += v.y;
            }
        }

        // ---- out_edges: mean-scale + Q3 + bias, ReLU, float2 store ----
        {
            float2 bo2v = *(const float2*)&sbo[c0];
            #pragma unroll
            for (int q = 0; q < 4; q++) {
                float2 t0 = unpk(acc[q][4]);
                float2 t1 = unpk(acc[q][5]);
                #pragma unroll
                for (int h = 0; h < 2; h++) {
                    int ri = 2*q + h;
                    int r  = r0t + ri;
                    if (r < w) {
                        float rc = srcp[r];
                        size_t orow = (ebase + r)*64;
                        float vx = (ex0[ri] + cc0)*rc + (h ? t0.y : t0.x) + bo2v.x;
                        float vy = (ex1[ri] + cc1)*rc + (h ? t1.y : t1.x) + bo2v.y;
                        float2 o; o.x = fmaxf(vx, 0.f); o.y = fmaxf(vy, 0.f);
                        *(float2*)&out_edges[orow + c0] = o;
                    }
                }
            }
        }

        float* t = curAT; curAT = nxtAT; nxtAT = t;
    }
}

// ---------------- K3: out_nodes; 256 blocks x 32-row tiles ----------------
__global__ void __launch_bounds__(256,2) k_outnodes(float* __restrict__ out,
                                                    const float* __restrict__ nodes,
                                                    const float* __restrict__ W_nodes,
                                                    const float* __restrict__ bias) {
    __shared__ float sW[128*64];
    __shared__ float sA[32][132];
    __shared__ float sb[64];
    for (int idx = threadIdx.x; idx < 128*64; idx += 256) sW[idx] = W_nodes[idx];
    if (threadIdx.x < 64) sb[threadIdx.x] = bias[threadIdx.x];
    int tx = threadIdx.x & 31, ty = threadIdx.x >> 5;
    int tile = blockIdx.x;                 // 256 tiles of 32 rows
    {
        const float4* sa = (const float4*)(g_agg + (size_t)tile*32*64);
        const float4* sn = (const float4*)(nodes + (size_t)tile*32*64);
        for (int idx = threadIdx.x; idx < 32*16; idx += 256) {
            int r = idx >> 4, q = idx & 15;
            ((float4*)&sA[r][0])[q]  = sa[idx];
            ((float4*)&sA[r][64])[q] = sn[idx];
        }
    }
    __syncthreads();
    float acc[4][2];
    #pragma unroll
    for (int a = 0; a < 4; a++) { acc[a][0] = 0.f; acc[a][1] = 0.f; }
    for (int j = 0; j < 128; j += 4) {
        float4 av[4];
        #pragma unroll
        for (int ri = 0; ri < 4; ri++) av[ri] = *(const float4*)&sA[ty*4 + ri][j];
        #pragma unroll
        for (int jj = 0; jj < 4; jj++) {
            float w0 = sW[(j+jj)*64 + tx];
            float w1 = sW[(j+jj)*64 + tx + 32];
            #pragma unroll
            for (int ri = 0; ri < 4; ri++) {
                float a = (jj==0) ? av[ri].x : (jj==1) ? av[ri].y : (jj==2) ? av[ri].z : av[ri].w;
                acc[ri][0] += a * w0;
                acc[ri][1] += a * w1;
            }
        }
    }
    #pragma unroll
    for (int ri = 0; ri < 4; ri++) {
        size_t row = (size_t)tile*32 + ty*4 + ri;
        float v0 = acc[ri][0] + sb[tx];
        float v1 = acc[ri][1] + sb[tx+32];
        out[row*64 + tx]      = v0 > 0.f ? v0 : 0.f;
        out[row*64 + tx + 32] = v1 > 0.f ? v1 : 0.f;
    }
}

// ---------------- launch ----------------
extern "C" void kernel_launch(void* const* d_in, const int* in_sizes, int n_in,
                              void* d_out, int out_size) {
    const float* input_nodes = (const float*)d_in[0];
    const float* input_edges = (const float*)d_in[1];
    const float* Wn1 = (const float*)d_in[2];
    const float* bn1 = (const float*)d_in[3];
    const float* Wn2 = (const float*)d_in[4];
    const float* bn2 = (const float*)d_in[5];
    const float* We1 = (const float*)d_in[6];
    const float* be1 = (const float*)d_in[7];
    const float* We2 = (const float*)d_in[8];
    const float* be2 = (const float*)d_in[9];
    const float* W_nodes    = (const float*)d_in[10];
    const float* W_edges    = (const float*)d_in[11];
    const float* bias_edges = (const float*)d_in[12];

    float* out       = (float*)d_out;
    float* out_nodes = out;
    float* out_edges = out + (size_t)Bq*Nn*64;

    cudaFuncSetAttribute(k_fusededge, cudaFuncAttributeMaxDynamicSharedMemorySize, SMEM_BYTES);

    k_prep<<<(2*64*192 + 128 + 255)/256, 256>>>(We1, We2, be1, be2, Wn1, bn1, Wn2, bn2, W_edges);
    k_nodeproj<<<512, 256>>>(input_nodes);
    k_fusededge<<<GRID, 512, SMEM_BYTES>>>(input_edges, W_edges, bias_edges, out_edges);
    k_outnodes<<<256, 256>>>(out_nodes, input_nodes, W_nodes, bias_edges);
}

// round 14
// speedup vs baseline: 1.3721x; 1.3721x over previous
#include <cuda_runtime.h>

#define Bq 8
#define Nn 1024
#define Mw 64
#define Ee 63456
#define NROWS (Bq*Nn)          /* 8192 node rows */
#define NTASK (Bq*Nn)

#define GRID    152
#define NSTREAM (GRID*2)       /* 304 task streams */

typedef unsigned long long ull;

// ---------------- device scratch ----------------
__device__ float g_Wcat[64*192];        // edge-side:  [We_edge | Wn_edge | W_e_edge]
__device__ float g_WcatP[64*192];       // node-side:  [We_src  | Wn_src  | Wn_dst ]
__device__ float g_be[64];
__device__ float g_bn[64];
__device__ float g_P[NROWS*192];        // node projections [Pes | Pns | Pnd]
__device__ float g_agg[NROWS*64];       // agg_n

__device__ __forceinline__ int node_w(int i)      { return i < Mw ? i : Mw; }
__device__ __forceinline__ int node_start(int i)  { return i <= Mw ? (i*(i-1))/2 : 2016 + (i-Mw)*Mw; }

// ---------------- packed fp32x2 helpers ----------------
__device__ __forceinline__ void fma2(ull &d, ull a, ull b) {
    asm("fma.rn.f32x2 %0, %1, %2, %0;" : "+l"(d) : "l"(a), "l"(b));
}
__device__ __forceinline__ ull bcast2(float x) {
    ull r; asm("mov.b64 %0, {%1, %1};" : "=l"(r) : "f"(x)); return r;
}
__device__ __forceinline__ float2 unpk(ull v) {
    float2 r; asm("mov.b64 {%0, %1}, %2;" : "=f"(r.x), "=f"(r.y) : "l"(v)); return r;
}
__device__ __forceinline__ ull pk(float x, float y) {
    ull r; asm("mov.b64 %0, {%1, %2};" : "=l"(r) : "f"(x), "f"(y)); return r;
}
__device__ __forceinline__ void gbar(int id) {
    asm volatile("bar.sync %0, %1;" :: "r"(id), "r"(256) : "memory");
}
// pinned-placement vector load (volatile: ptxas cannot sink it)
__device__ __forceinline__ float2 ldg2v(const float* p) {
    float2 v;
    asm volatile("ld.global.nc.v2.f32 {%0, %1}, [%2];" : "=f"(v.x), "=f"(v.y) : "l"(p));
    return v;
}

// ---------------- shared layout (floats); tile stride 68 (16B-aligned rows) ----------------
#define STRD     68
#define SZ_AT    (64*STRD)     /* 4352 */
#define OFF_W1   0             /* 12288 */
#define OFF_W2   12288         /* 4096  */
#define OFF_BE   16384
#define OFF_BN   16448
#define OFF_BO   16512
#define OFF_RCP  16576
#define OFF_AT   16640         /* [2 grp][2 buf][4352] = 17408 */
#define OFF_PET  34048         /* [2 grp][4352] = 8704 */
#define OFF_SRED 42752         /* [2 grp][2 par][512] = 2048 */
#define OFF_SWR  44800         /* [2 grp][2 par][256 ull] = 2048 floats */
#define SMEM_FLOATS 46848
#define SMEM_BYTES  (SMEM_FLOATS*4)

// ---------------- K0: build fused weight blocks directly (ILP-4 dot products) ----------------
__global__ void k_prep(const float* __restrict__ We1, const float* __restrict__ We2,
                       const float* __restrict__ be1, const float* __restrict__ be2,
                       const float* __restrict__ Wn1, const float* __restrict__ bn1,
                       const float* __restrict__ Wn2, const float* __restrict__ bn2,
                       const float* __restrict__ W_edges) {
    int idx = blockIdx.x*blockDim.x + threadIdx.x;
    if (idx < 64*192) {
        int j = idx / 192, c = idx % 192;
        float v;
        if (c < 64) {
            float s0=0.f,s1=0.f,s2=0.f,s3=0.f;
            const float* a = We1 + (64+j)*128;
            for (int t = 0; t < 128; t += 4) {
                s0 += a[t+0]*We2[(t+0)*64+c]; s1 += a[t+1]*We2[(t+1)*64+c];
                s2 += a[t+2]*We2[(t+2)*64+c]; s3 += a[t+3]*We2[(t+3)*64+c];
            }
            v = (s0+s1)+(s2+s3);
        } else if (c < 128) {
            int cc = c - 64;
            float s0=0.f,s1=0.f,s2=0.f,s3=0.f;
            const float* a = Wn1 + (128+j)*128;
            for (int t = 0; t < 128; t += 4) {
                s0 += a[t+0]*Wn2[(t+0)*64+cc]; s1 += a[t+1]*Wn2[(t+1)*64+cc];
                s2 += a[t+2]*Wn2[(t+2)*64+cc]; s3 += a[t+3]*Wn2[(t+3)*64+cc];
            }
            v = (s0+s1)+(s2+s3);
        } else {
            v = W_edges[(64+j)*64 + (c-128)];
        }
        g_Wcat[idx] = v;
        return;
    }
    int i2 = idx - 64*192;
    if (i2 >= 0 && i2 < 64*192) {
        int j = i2 / 192, c = i2 % 192;
        const float* a; const float* B; int cc;
        if (c < 64)       { a = We1 + j*128;      B = We2; cc = c; }
        else if (c < 128) { a = Wn1 + j*128;      B = Wn2; cc = c - 64; }
        else              { a = Wn1 + (64+j)*128; B = Wn2; cc = c - 128; }
        float s0=0.f,s1=0.f,s2=0.f,s3=0.f;
        for (int t = 0; t < 128; t += 4) {
            s0 += a[t+0]*B[(t+0)*64+cc]; s1 += a[t+1]*B[(t+1)*64+cc];
            s2 += a[t+2]*B[(t+2)*64+cc]; s3 += a[t+3]*B[(t+3)*64+cc];
        }
        g_WcatP[i2] = (s0+s1)+(s2+s3);
        return;
    }
    int i3 = idx - 2*64*192;
    if (i3 >= 0 && i3 < 64) {
        float s = be2[i3];
        for (int t = 0; t < 128; t++) s += be1[t]*We2[t*64+i3];
        g_be[i3] = s;
    } else if (i3 >= 64 && i3 < 128) {
        int c = i3 - 64; float s = bn2[c];
        for (int t = 0; t < 128; t++) s += bn1[t]*Wn2[t*64+c];
        g_bn[c] = s;
    }
}

// ---------------- K1: node projections GEMM; 512 blocks x 16-row tiles ----------------
__global__ void __launch_bounds__(256,2) k_nodeproj(const float* __restrict__ A) {
    __shared__ float sW[64*192];
    __shared__ float sA[16][68];
    for (int idx = threadIdx.x; idx < 64*192; idx += 256) sW[idx] = g_WcatP[idx];
    int tx = threadIdx.x & 31, ty = threadIdx.x >> 5;
    int tile = blockIdx.x;                 // 512 tiles of 16 rows
    if (threadIdx.x < 16*16) {
        const float4* src = (const float4*)(A + (size_t)tile*16*64);
        int r = threadIdx.x >> 4, q = threadIdx.x & 15;
        ((float4*)&sA[r][0])[q] = src[threadIdx.x];
    }
    __syncthreads();
    float acc[2][6];
    #pragma unroll
    for (int a = 0; a < 2; a++)
        #pragma unroll
        for (int b = 0; b < 6; b++) acc[a][b] = 0.f;
    for (int j = 0; j < 64; j += 4) {
        float4 av[2];
        #pragma unroll
        for (int ri = 0; ri < 2; ri++) av[ri] = *(const float4*)&sA[ty*2 + ri][j];
        #pragma unroll
        for (int jj = 0; jj < 4; jj++) {
            float wv[6];
            #pragma unroll
            for (int ci = 0; ci < 6; ci++) wv[ci] = sW[(j+jj)*192 + tx + 32*ci];
            #pragma unroll
            for (int ri = 0; ri < 2; ri++) {
                float a = (jj==0) ? av[ri].x : (jj==1) ? av[ri].y : (jj==2) ? av[ri].z : av[ri].w;
                #pragma unroll
                for (int ci = 0; ci < 6; ci++) acc[ri][ci] += a * wv[ci];
            }
        }
    }
    float* dst = g_P + (size_t)tile*16*192;
    #pragma unroll
    for (int ri = 0; ri < 2; ri++) {
        int r = ty*2 + ri;
        #pragma unroll
        for (int ci = 0; ci < 6; ci++)
            dst[(size_t)r*192 + tx + 32*ci] = acc[ri][ci];
    }
}

// ---------------- K2: fused pipeline (EXACT R12 structure: late barrier) ----------------
__global__ void __launch_bounds__(512,1) k_fusededge(const float* __restrict__ edges,
                                                     const float* __restrict__ W_edges,
                                                     const float* __restrict__ bias,
                                                     float* __restrict__ out_edges) {
    extern __shared__ float sm[];
    float* sW1  = sm + OFF_W1;
    float* sW2  = sm + OFF_W2;
    float* sbe  = sm + OFF_BE;
    float* sbn  = sm + OFF_BN;
    float* sbo  = sm + OFF_BO;
    float* srcp = sm + OFF_RCP;
    int tid = threadIdx.x;

    for (int idx = tid; idx < 64*192; idx += 512) sW1[idx] = g_Wcat[idx];
    for (int idx = tid; idx < 64*64;  idx += 512) sW2[idx] = W_edges[idx];
    if (tid < 64) {
        sbe[tid] = g_be[tid];
        sbn[tid] = g_bn[tid];
        sbo[tid] = bias[tid];
        srcp[tid] = 1.0f / (float)(tid > 0 ? tid : 1);
    }
    __syncthreads();

    int grp  = tid >> 8;            // warp-group 0/1
    int gtid = tid & 255;
    int tx = gtid & 31, ty = gtid >> 5;
    int bar = grp + 1;
    int r0t = 8*ty;                 // this warp's first row
    int c0 = 2*tx;                  // this thread's first col per 64-segment

    float* sPeT  = sm + OFF_PET  + grp*SZ_AT;
    float* bufA  = sm + OFF_AT + (grp*2+0)*SZ_AT;
    float* bufB  = sm + OFF_AT + (grp*2+1)*SZ_AT;
    float* sredB = sm + OFF_SRED + grp*1024;
    ull*   swrB  = (ull*)(sm + OFF_SWR) + grp*512;

    int task = blockIdx.x*2 + grp;

    // ---- prologue: own-warp rows of first tile ----
    {
        int b = task >> 10, i = task & 1023;
        size_t ebase = (size_t)b*Ee + node_start(i);
        const float4* src = (const float4*)(edges + ebase*64);
        #pragma unroll
        for (int k = 0; k < 4; k++) {
            int idx = tx + 32*k;
            int rl = idx >> 4, q = idx & 15;
            float4 v = __ldg(src + (r0t + rl)*16 + q);
            int j = 4*q, r = r0t + rl;
            bufA[(j+0)*STRD + r] = v.x; bufA[(j+1)*STRD + r] = v.y;
            bufA[(j+2)*STRD + r] = v.z; bufA[(j+3)*STRD + r] = v.w;
        }
    }
    __syncwarp();

    // ---- de-phase the two warp-groups by ~half a task-round (verified) ----
    if (grp == 1) {
        long long t0 = clock64();
        while (clock64() - t0 < 8000) {}
    }

    float* curAT = bufA;
    float* nxtAT = bufB;
    int par = 0;

    for (; task < NTASK; task += NSTREAM, par ^= 1) {
        int b = task >> 10, i = task & 1023;
        int w = node_w(i), ns = node_start(i);
        size_t ebase = (size_t)b*Ee + ns;
        int srow0 = (b << 10) + (i - w);
        int ntask = task + NSTREAM;
        bool hasn = ntask < NTASK;
        float* sredW = sredB + par*512;
        ull*   swrW  = swrB + par*256;

        // ---- GEMM1 part A: j = 0..47 ----
        ull acc[4][6];
        #pragma unroll
        for (int q = 0; q < 4; q++)
            #pragma unroll
            for (int c2 = 0; c2 < 6; c2++) acc[q][c2] = 0ull;
        #pragma unroll 8
        for (int j = 0; j < 48; j++) {
            ulonglong2 aA = *(const ulonglong2*)&curAT[j*STRD + r0t];
            ulonglong2 aB = *(const ulonglong2*)&curAT[j*STRD + r0t + 4];
            ull a2[4] = {aA.x, aA.y, aB.x, aB.y};
            #pragma unroll
            for (int g = 0; g < 3; g++) {
                float2 wp = *(const float2*)&sW1[j*192 + 64*g + c0];
                ull w20 = bcast2(wp.x);
                ull w21 = bcast2(wp.y);
                #pragma unroll
                for (int q = 0; q < 4; q++) {
                    fma2(acc[q][2*g+0], a2[q], w20);
                    fma2(acc[q][2*g+1], a2[q], w21);
                }
            }
        }

        // ---- issue g_P loads NOW (covered by remaining 16 j-iters) ----
        float2 pnd, pfe[8], pfn[8];
        {
            size_t pb = (size_t)task*192;
            pnd = ldg2v(&g_P[pb + 128 + c0]);
            #pragma unroll
            for (int ri = 0; ri < 8; ri++) {
                size_t sr = (size_t)(srow0 + r0t + ri)*192;
                pfe[ri] = ldg2v(&g_P[sr + c0]);
                pfn[ri] = ldg2v(&g_P[sr + 64 + c0]);
            }
        }

        // ---- GEMM1 part B: j = 48..63 ----
        #pragma unroll 8
        for (int j = 48; j < 64; j++) {
            ulonglong2 aA = *(const ulonglong2*)&curAT[j*STRD + r0t];
            ulonglong2 aB = *(const ulonglong2*)&curAT[j*STRD + r0t + 4];
            ull a2[4] = {aA.x, aA.y, aB.x, aB.y};
            #pragma unroll
            for (int g = 0; g < 3; g++) {
                float2 wp = *(const float2*)&sW1[j*192 + 64*g + c0];
                ull w20 = bcast2(wp.x);
                ull w21 = bcast2(wp.y);
                #pragma unroll
                for (int q = 0; q < 4; q++) {
                    fma2(acc[q][2*g+0], a2[q], w20);
                    fma2(acc[q][2*g+1], a2[q], w21);
                }
            }
        }

        float2 be2v = *(const float2*)&sbe[c0];
        float2 bn2v = *(const float2*)&sbn[c0];

        // ---- epilogue: ReLU; pair_e -> sPeT (warp-local rows); pair_n partials ----
        float np0 = 0.f, np1 = 0.f;
        #pragma unroll
        for (int q = 0; q < 4; q++) {
            int rA = 2*q, rB = 2*q + 1;
            int gA = (r0t + rA) < w, gB = (r0t + rB) < w;
            float2 e0 = unpk(acc[q][0]);
            float2 e1 = unpk(acc[q][1]);
            float2 n0 = unpk(acc[q][2]);
            float2 n1 = unpk(acc[q][3]);
            float p0A = e0.x + pfe[rA].x + be2v.x;
            float p0B = e0.y + pfe[rB].x + be2v.x;
            p0A = (gA && p0A > 0.f) ? p0A : 0.f;
            p0B = (gB && p0B > 0.f) ? p0B : 0.f;
            *(ull*)&sPeT[(c0+0)*STRD + r0t + rA] = pk(p0A, p0B);
            float p1A = e1.x + pfe[rA].y + be2v.y;
            float p1B = e1.y + pfe[rB].y + be2v.y;
            p1A = (gA && p1A > 0.f) ? p1A : 0.f;
            p1B = (gB && p1B > 0.f) ? p1B : 0.f;
            *(ull*)&sPeT[(c0+1)*STRD + r0t + rA] = pk(p1A, p1B);
            float q0A = n0.x + pfn[rA].x + pnd.x + bn2v.x;
            float q0B = n0.y + pfn[rB].x + pnd.x + bn2v.x;
            if (gA && q0A > 0.f) np0 += q0A;
            if (gB && q0B > 0.f) np0 += q0B;
            float q1A = n1.x + pfn[rA].y + pnd.y + bn2v.y;
            float q1B = n1.y + pfn[rB].y + pnd.y + bn2v.y;
            if (gA && q1A > 0.f) np1 += q1A;
            if (gB && q1B > 0.f) np1 += q1B;
        }
        *(ull*)&sredW[ty*64 + c0] = pk(np0, np1);

        // ---- prefetch next tile (own-warp rows; LDGs fly under GEMM2) ----
        float4 pf4[4];
        if (hasn) {
            int nb = ntask >> 10, ni = ntask & 1023;
            size_t nebase = (size_t)nb*Ee + node_start(ni);
            const float4* nsrc = (const float4*)(edges + nebase*64);
            #pragma unroll
            for (int k = 0; k < 4; k++) {
                int idx = tx + 32*k;
                pf4[k] = __ldg(nsrc + (r0t + (idx >> 4))*16 + (idx & 15));
            }
        }
        __syncwarp();                        // sPeT rows are warp-local

        // ---- GEMM2: R = pair_e @ W_mean (own sPeT rows) ----
        ull acc20[4], acc21[4];
        #pragma unroll
        for (int p = 0; p < 4; p++) { acc20[p] = 0ull; acc21[p] = 0ull; }
        #pragma unroll 8
        for (int j = 0; j < 64; j++) {
            ulonglong2 aA = *(const ulonglong2*)&sPeT[j*STRD + r0t];
            ulonglong2 aB = *(const ulonglong2*)&sPeT[j*STRD + r0t + 4];
            ull a2[4] = {aA.x, aA.y, aB.x, aB.y};
            float2 wp = *(const float2*)&sW2[j*64 + c0];
            ull w20 = bcast2(wp.x);
            ull w21 = bcast2(wp.y);
            #pragma unroll
            for (int q = 0; q < 4; q++) {
                fma2(acc20[q], a2[q], w20);
                fma2(acc21[q], a2[q], w21);
            }
        }

        // ---- exclusive row-prefix (in-register) + warp totals ----
        float s0[8], s1[8];
        #pragma unroll
        for (int q = 0; q < 4; q++) {
            float2 v0 = unpk(acc20[q]);
            float2 v1 = unpk(acc21[q]);
            s0[2*q] = v0.x; s0[2*q+1] = v0.y;
            s1[2*q] = v1.x; s1[2*q+1] = v1.y;
        }
        float ex0[8], ex1[8], run0 = 0.f, run1 = 0.f;
        #pragma unroll
        for (int ri = 0; ri < 8; ri++) {
            ex0[ri] = run0; run0 += s0[ri];
            ex1[ri] = run1; run1 += s1[ri];
        }
        swrW[ty*32 + tx] = pk(run0, run1);

        // ---- store prefetched tile into alternate buffer (own rows) ----
        if (hasn) {
            #pragma unroll
            for (int k = 0; k < 4; k++) {
                int idx = tx + 32*k;
                int r = r0t + (idx >> 4), j = 4*(idx & 15);
                nxtAT[(j+0)*STRD + r] = pf4[k].x; nxtAT[(j+1)*STRD + r] = pf4[k].y;
                nxtAT[(j+2)*STRD + r] = pf4[k].z; nxtAT[(j+3)*STRD + r] = pf4[k].w;
            }
        }

        gbar(bar);                           // single group barrier: sred/swr visible

        // ---- warp-carry (predicated, unrolled) ----
        float cc0 = 0.f, cc1 = 0.f;
        #pragma unroll
        for (int t = 0; t < 7; t++) {
            if (t < ty) {
                float2 v = unpk(swrW[t*32 + tx]);
                cc0 += v.x; cc1 += v.y;
            }
        }

        // ---- out_edges: mean-scale + Q3 + bias, ReLU, float2 store ----
        {
            float2 bo2v = *(const float2*)&sbo[c0];
            #pragma unroll
            for (int q = 0; q < 4; q++) {
                float2 t0 = unpk(acc[q][4]);
                float2 t1 = unpk(acc[q][5]);
                #pragma unroll
                for (int h = 0; h < 2; h++) {
                    int ri = 2*q + h;
                    int r  = r0t + ri;
                    if (r < w) {
                        float rc = srcp[r];
                        size_t orow = (ebase + r)*64;
                        float vx = (ex0[ri] + cc0)*rc + (h ? t0.y : t0.x) + bo2v.x;
                        float vy = (ex1[ri] + cc1)*rc + (h ? t1.y : t1.x) + bo2v.y;
                        float2 o; o.x = fmaxf(vx, 0.f); o.y = fmaxf(vy, 0.f);
                        *(float2*)&out_edges[orow + c0] = o;
                    }
                }
            }
        }

        // ---- agg_n write (64 threads; no extra barrier needed) ----
        if (gtid < 64) {
            int c = gtid;
            float a = 0.f;
            #pragma unroll
            for (int t = 0; t < 8; t++) a += sredW[t*64 + c];
            g_agg[(size_t)task*64 + c] = a * (1.0f / (float)(w > 0 ? w : 1));
        }

        float* t = curAT; curAT = nxtAT; nxtAT = t;
    }
}

// ---------------- K3: out_nodes; 256 blocks x 32-row tiles ----------------
__global__ void __launch_bounds__(256,2) k_outnodes(float* __restrict__ out,
                                                    const float* __restrict__ nodes,
                                                    const float* __restrict__ W_nodes,
                                                    const float* __restrict__ bias) {
    __shared__ float sW[128*64];
    __shared__ float sA[32][132];
    __shared__ float sb[64];
    for (int idx = threadIdx.x; idx < 128*64; idx += 256) sW[idx] = W_nodes[idx];
    if (threadIdx.x < 64) sb[threadIdx.x] = bias[threadIdx.x];
    int tx = threadIdx.x & 31, ty = threadIdx.x >> 5;
    int tile = blockIdx.x;                 // 256 tiles of 32 rows
    {
        const float4* sa = (const float4*)(g_agg + (size_t)tile*32*64);
        const float4* sn = (const float4*)(nodes + (size_t)tile*32*64);
        for (int idx = threadIdx.x; idx < 32*16; idx += 256) {
            int r = idx >> 4, q = idx & 15;
            ((float4*)&sA[r][0])[q]  = sa[idx];
            ((float4*)&sA[r][64])[q] = sn[idx];
        }
    }
    __syncthreads();
    float acc[4][2];
    #pragma unroll
    for (int a = 0; a < 4; a++) { acc[a][0] = 0.f; acc[a][1] = 0.f; }
    for (int j = 0; j < 128; j += 4) {
        float4 av[4];
        #pragma unroll
        for (int ri = 0; ri < 4; ri++) av[ri] = *(const float4*)&sA[ty*4 + ri][j];
        #pragma unroll
        for (int jj = 0; jj < 4; jj++) {
            float w0 = sW[(j+jj)*64 + tx];
            float w1 = sW[(j+jj)*64 + tx + 32];
            #pragma unroll
            for (int ri = 0; ri < 4; ri++) {
                float a = (jj==0) ? av[ri].x : (jj==1) ? av[ri].y : (jj==2) ? av[ri].z : av[ri].w;
                acc[ri][0] += a * w0;
                acc[ri][1] += a * w1;
            }
        }
    }
    #pragma unroll
    for (int ri = 0; ri < 4; ri++) {
        size_t row = (size_t)tile*32 + ty*4 + ri;
        float v0 = acc[ri][0] + sb[tx];
        float v1 = acc[ri][1] + sb[tx+32];
        out[row*64 + tx]      = v0 > 0.f ? v0 : 0.f;
        out[row*64 + tx + 32] = v1 > 0.f ? v1 : 0.f;
    }
}

// ---------------- launch ----------------
extern "C" void kernel_launch(void* const* d_in, const int* in_sizes, int n_in,
                              void* d_out, int out_size) {
    const float* input_nodes = (const float*)d_in[0];
    const float* input_edges = (const float*)d_in[1];
    const float* Wn1 = (const float*)d_in[2];
    const float* bn1 = (const float*)d_in[3];
    const float* Wn2 = (const float*)d_in[4];
    const float* bn2 = (const float*)d_in[5];
    const float* We1 = (const float*)d_in[6];
    const float* be1 = (const float*)d_in[7];
    const float* We2 = (const float*)d_in[8];
    const float* be2 = (const float*)d_in[9];
    const float* W_nodes    = (const float*)d_in[10];
    const float* W_edges    = (const float*)d_in[11];
    const float* bias_edges = (const float*)d_in[12];

    float* out       = (float*)d_out;
    float* out_nodes = out;
    float* out_edges = out + (size_t)Bq*Nn*64;

    cudaFuncSetAttribute(k_fusededge, cudaFuncAttributeMaxDynamicSharedMemorySize, SMEM_BYTES);

    k_prep<<<(2*64*192 + 128 + 255)/256, 256>>>(We1, We2, be1, be2, Wn1, bn1, Wn2, bn2, W_edges);
    k_nodeproj<<<512, 256>>>(input_nodes);
    k_fusededge<<<GRID, 512, SMEM_BYTES>>>(input_edges, W_edges, bias_edges, out_edges);
    k_outnodes<<<256, 256>>>(out_nodes, input_nodes, W_nodes, bias_edges);
}

// round 15
// speedup vs baseline: 1.3809x; 1.0064x over previous
#include <cuda_runtime.h>

#define Bq 8
#define Nn 1024
#define Mw 64
#define Ee 63456
#define NROWS (Bq*Nn)          /* 8192 node rows */
#define NTASK (Bq*Nn)

#define GRID    152
#define NSTREAM (GRID*2)       /* 304 task streams */

typedef unsigned long long ull;

// ---------------- device scratch ----------------
__device__ float g_Wcat[64*192];        // edge-side:  [We_edge | Wn_edge | W_e_edge]
__device__ float g_WcatP[64*192];       // node-side:  [We_src  | Wn_src  | Wn_dst ]
__device__ float g_be[64];
__device__ float g_bn[64];
__device__ float g_P[NROWS*192];        // node projections [Pes | Pns | Pnd]
__device__ float g_agg[NROWS*64];       // agg_n

__device__ __forceinline__ int node_w(int i)      { return i < Mw ? i : Mw; }
__device__ __forceinline__ int node_start(int i)  { return i <= Mw ? (i*(i-1))/2 : 2016 + (i-Mw)*Mw; }

// ---------------- packed fp32x2 helpers ----------------
__device__ __forceinline__ void fma2(ull &d, ull a, ull b) {
    asm("fma.rn.f32x2 %0, %1, %2, %0;" : "+l"(d) : "l"(a), "l"(b));
}
__device__ __forceinline__ ull bcast2(float x) {
    ull r; asm("mov.b64 %0, {%1, %1};" : "=l"(r) : "f"(x)); return r;
}
__device__ __forceinline__ float2 unpk(ull v) {
    float2 r; asm("mov.b64 {%0, %1}, %2;" : "=f"(r.x), "=f"(r.y) : "l"(v)); return r;
}
__device__ __forceinline__ ull pk(float x, float y) {
    ull r; asm("mov.b64 %0, {%1, %2};" : "=l"(r) : "f"(x), "f"(y)); return r;
}
__device__ __forceinline__ void gbar(int id) {
    asm volatile("bar.sync %0, %1;" :: "r"(id), "r"(256) : "memory");
}
// pinned-placement vector load (volatile: ptxas cannot sink it)
__device__ __forceinline__ float2 ldg2v(const float* p) {
    float2 v;
    asm volatile("ld.global.nc.v2.f32 {%0, %1}, [%2];" : "=f"(v.x), "=f"(v.y) : "l"(p));
    return v;
}

// ---------------- shared layout (floats); tile stride 68 (16B-aligned rows) ----------------
#define STRD     68
#define SZ_AT    (64*STRD)     /* 4352 */
#define OFF_W1   0             /* 12288 */
#define OFF_W2   12288         /* 4096  */
#define OFF_BE   16384
#define OFF_BN   16448
#define OFF_BO   16512
#define OFF_RCP  16576
#define OFF_AT   16640         /* [2 grp][2 buf][4352] = 17408 */
#define OFF_PET  34048         /* [2 grp][4352] = 8704 */
#define OFF_SRED 42752         /* [2 grp][2 par][512] = 2048 */
#define OFF_SWR  44800         /* [2 grp][2 par][256 ull] = 2048 floats */
#define SMEM_FLOATS 46848
#define SMEM_BYTES  (SMEM_FLOATS*4)

// ---------------- K0: build fused weight blocks directly (ILP-4 dot products) ----------------
__global__ void k_prep(const float* __restrict__ We1, const float* __restrict__ We2,
                       const float* __restrict__ be1, const float* __restrict__ be2,
                       const float* __restrict__ Wn1, const float* __restrict__ bn1,
                       const float* __restrict__ Wn2, const float* __restrict__ bn2,
                       const float* __restrict__ W_edges) {
    int idx = blockIdx.x*blockDim.x + threadIdx.x;
    if (idx < 64*192) {
        int j = idx / 192, c = idx % 192;
        float v;
        if (c < 64) {
            float s0=0.f,s1=0.f,s2=0.f,s3=0.f;
            const float* a = We1 + (64+j)*128;
            for (int t = 0; t < 128; t += 4) {
                s0 += a[t+0]*We2[(t+0)*64+c]; s1 += a[t+1]*We2[(t+1)*64+c];
                s2 += a[t+2]*We2[(t+2)*64+c]; s3 += a[t+3]*We2[(t+3)*64+c];
            }
            v = (s0+s1)+(s2+s3);
        } else if (c < 128) {
            int cc = c - 64;
            float s0=0.f,s1=0.f,s2=0.f,s3=0.f;
            const float* a = Wn1 + (128+j)*128;
            for (int t = 0; t < 128; t += 4) {
                s0 += a[t+0]*Wn2[(t+0)*64+cc]; s1 += a[t+1]*Wn2[(t+1)*64+cc];
                s2 += a[t+2]*Wn2[(t+2)*64+cc]; s3 += a[t+3]*Wn2[(t+3)*64+cc];
            }
            v = (s0+s1)+(s2+s3);
        } else {
            v = W_edges[(64+j)*64 + (c-128)];
        }
        g_Wcat[idx] = v;
        return;
    }
    int i2 = idx - 64*192;
    if (i2 >= 0 && i2 < 64*192) {
        int j = i2 / 192, c = i2 % 192;
        const float* a; const float* B; int cc;
        if (c < 64)       { a = We1 + j*128;      B = We2; cc = c; }
        else if (c < 128) { a = Wn1 + j*128;      B = Wn2; cc = c - 64; }
        else              { a = Wn1 + (64+j)*128; B = Wn2; cc = c - 128; }
        float s0=0.f,s1=0.f,s2=0.f,s3=0.f;
        for (int t = 0; t < 128; t += 4) {
            s0 += a[t+0]*B[(t+0)*64+cc]; s1 += a[t+1]*B[(t+1)*64+cc];
            s2 += a[t+2]*B[(t+2)*64+cc]; s3 += a[t+3]*B[(t+3)*64+cc];
        }
        g_WcatP[i2] = (s0+s1)+(s2+s3);
        return;
    }
    int i3 = idx - 2*64*192;
    if (i3 >= 0 && i3 < 64) {
        float s = be2[i3];
        for (int t = 0; t < 128; t++) s += be1[t]*We2[t*64+i3];
        g_be[i3] = s;
    } else if (i3 >= 64 && i3 < 128) {
        int c = i3 - 64; float s = bn2[c];
        for (int t = 0; t < 128; t++) s += bn1[t]*Wn2[t*64+c];
        g_bn[c] = s;
    }
}

// ---------------- K1: node projections GEMM; 256 blocks x 32-row tiles (R12 config) ----------------
__global__ void __launch_bounds__(256,2) k_nodeproj(const float* __restrict__ A) {
    __shared__ float sW[64*192];
    __shared__ float sA[32][68];
    for (int idx = threadIdx.x; idx < 64*192; idx += 256) sW[idx] = g_WcatP[idx];
    int tx = threadIdx.x & 31, ty = threadIdx.x >> 5;
    int tile = blockIdx.x;                 // 256 tiles of 32 rows
    {
        const float4* src = (const float4*)(A + (size_t)tile*32*64);
        for (int idx = threadIdx.x; idx < 32*16; idx += 256) {
            int r = idx >> 4, q = idx & 15;
            ((float4*)&sA[r][0])[q] = src[idx];
        }
    }
    __syncthreads();
    float acc[4][6];
    #pragma unroll
    for (int a = 0; a < 4; a++)
        #pragma unroll
        for (int b = 0; b < 6; b++) acc[a][b] = 0.f;
    for (int j = 0; j < 64; j += 4) {
        float4 av[4];
        #pragma unroll
        for (int ri = 0; ri < 4; ri++) av[ri] = *(const float4*)&sA[ty*4 + ri][j];
        #pragma unroll
        for (int jj = 0; jj < 4; jj++) {
            float wv[6];
            #pragma unroll
            for (int ci = 0; ci < 6; ci++) wv[ci] = sW[(j+jj)*192 + tx + 32*ci];
            #pragma unroll
            for (int ri = 0; ri < 4; ri++) {
                float a = (jj==0) ? av[ri].x : (jj==1) ? av[ri].y : (jj==2) ? av[ri].z : av[ri].w;
                #pragma unroll
                for (int ci = 0; ci < 6; ci++) acc[ri][ci] += a * wv[ci];
            }
        }
    }
    float* dst = g_P + (size_t)tile*32*192;
    #pragma unroll
    for (int ri = 0; ri < 4; ri++) {
        int r = ty*4 + ri;
        #pragma unroll
        for (int ci = 0; ci < 6; ci++)
            dst[(size_t)r*192 + tx + 32*ci] = acc[ri][ci];
    }
}

// ---------------- K2: fused pipeline (EXACT R12 structure: late barrier) ----------------
__global__ void __launch_bounds__(512,1) k_fusededge(const float* __restrict__ edges,
                                                     const float* __restrict__ W_edges,
                                                     const float* __restrict__ bias,
                                                     float* __restrict__ out_edges) {
    extern __shared__ float sm[];
    float* sW1  = sm + OFF_W1;
    float* sW2  = sm + OFF_W2;
    float* sbe  = sm + OFF_BE;
    float* sbn  = sm + OFF_BN;
    float* sbo  = sm + OFF_BO;
    float* srcp = sm + OFF_RCP;
    int tid = threadIdx.x;

    for (int idx = tid; idx < 64*192; idx += 512) sW1[idx] = g_Wcat[idx];
    for (int idx = tid; idx < 64*64;  idx += 512) sW2[idx] = W_edges[idx];
    if (tid < 64) {
        sbe[tid] = g_be[tid];
        sbn[tid] = g_bn[tid];
        sbo[tid] = bias[tid];
        srcp[tid] = 1.0f / (float)(tid > 0 ? tid : 1);
    }
    __syncthreads();

    int grp  = tid >> 8;            // warp-group 0/1
    int gtid = tid & 255;
    int tx = gtid & 31, ty = gtid >> 5;
    int bar = grp + 1;
    int r0t = 8*ty;                 // this warp's first row
    int c0 = 2*tx;                  // this thread's first col per 64-segment

    float* sPeT  = sm + OFF_PET  + grp*SZ_AT;
    float* bufA  = sm + OFF_AT + (grp*2+0)*SZ_AT;
    float* bufB  = sm + OFF_AT + (grp*2+1)*SZ_AT;
    float* sredB = sm + OFF_SRED + grp*1024;
    ull*   swrB  = (ull*)(sm + OFF_SWR) + grp*512;

    int task = blockIdx.x*2 + grp;

    // ---- prologue: own-warp rows of first tile ----
    {
        int b = task >> 10, i = task & 1023;
        size_t ebase = (size_t)b*Ee + node_start(i);
        const float4* src = (const float4*)(edges + ebase*64);
        #pragma unroll
        for (int k = 0; k < 4; k++) {
            int idx = tx + 32*k;
            int rl = idx >> 4, q = idx & 15;
            float4 v = __ldg(src + (r0t + rl)*16 + q);
            int j = 4*q, r = r0t + rl;
            bufA[(j+0)*STRD + r] = v.x; bufA[(j+1)*STRD + r] = v.y;
            bufA[(j+2)*STRD + r] = v.z; bufA[(j+3)*STRD + r] = v.w;
        }
    }
    __syncwarp();

    // ---- de-phase the two warp-groups by ~half a task-round (verified) ----
    if (grp == 1) {
        long long t0 = clock64();
        while (clock64() - t0 < 8000) {}
    }

    float* curAT = bufA;
    float* nxtAT = bufB;
    int par = 0;

    for (; task < NTASK; task += NSTREAM, par ^= 1) {
        int b = task >> 10, i = task & 1023;
        int w = node_w(i), ns = node_start(i);
        size_t ebase = (size_t)b*Ee + ns;
        int srow0 = (b << 10) + (i - w);
        int ntask = task + NSTREAM;
        bool hasn = ntask < NTASK;
        float* sredW = sredB + par*512;
        ull*   swrW  = swrB + par*256;

        // ---- GEMM1 part A: j = 0..47 ----
        ull acc[4][6];
        #pragma unroll
        for (int q = 0; q < 4; q++)
            #pragma unroll
            for (int c2 = 0; c2 < 6; c2++) acc[q][c2] = 0ull;
        #pragma unroll 8
        for (int j = 0; j < 48; j++) {
            ulonglong2 aA = *(const ulonglong2*)&curAT[j*STRD + r0t];
            ulonglong2 aB = *(const ulonglong2*)&curAT[j*STRD + r0t + 4];
            ull a2[4] = {aA.x, aA.y, aB.x, aB.y};
            #pragma unroll
            for (int g = 0; g < 3; g++) {
                float2 wp = *(const float2*)&sW1[j*192 + 64*g + c0];
                ull w20 = bcast2(wp.x);
                ull w21 = bcast2(wp.y);
                #pragma unroll
                for (int q = 0; q < 4; q++) {
                    fma2(acc[q][2*g+0], a2[q], w20);
                    fma2(acc[q][2*g+1], a2[q], w21);
                }
            }
        }

        // ---- issue g_P loads NOW (covered by remaining 16 j-iters) ----
        float2 pnd, pfe[8], pfn[8];
        {
            size_t pb = (size_t)task*192;
            pnd = ldg2v(&g_P[pb + 128 + c0]);
            #pragma unroll
            for (int ri = 0; ri < 8; ri++) {
                size_t sr = (size_t)(srow0 + r0t + ri)*192;
                pfe[ri] = ldg2v(&g_P[sr + c0]);
                pfn[ri] = ldg2v(&g_P[sr + 64 + c0]);
            }
        }

        // ---- GEMM1 part B: j = 48..63 ----
        #pragma unroll 8
        for (int j = 48; j < 64; j++) {
            ulonglong2 aA = *(const ulonglong2*)&curAT[j*STRD + r0t];
            ulonglong2 aB = *(const ulonglong2*)&curAT[j*STRD + r0t + 4];
            ull a2[4] = {aA.x, aA.y, aB.x, aB.y};
            #pragma unroll
            for (int g = 0; g < 3; g++) {
                float2 wp = *(const float2*)&sW1[j*192 + 64*g + c0];
                ull w20 = bcast2(wp.x);
                ull w21 = bcast2(wp.y);
                #pragma unroll
                for (int q = 0; q < 4; q++) {
                    fma2(acc[q][2*g+0], a2[q], w20);
                    fma2(acc[q][2*g+1], a2[q], w21);
                }
            }
        }

        float2 be2v = *(const float2*)&sbe[c0];
        float2 bn2v = *(const float2*)&sbn[c0];

        // ---- epilogue: ReLU; pair_e -> sPeT (warp-local rows); pair_n partials ----
        float np0 = 0.f, np1 = 0.f;
        #pragma unroll
        for (int q = 0; q < 4; q++) {
            int rA = 2*q, rB = 2*q + 1;
            int gA = (r0t + rA) < w, gB = (r0t + rB) < w;
            float2 e0 = unpk(acc[q][0]);
            float2 e1 = unpk(acc[q][1]);
            float2 n0 = unpk(acc[q][2]);
            float2 n1 = unpk(acc[q][3]);
            float p0A = e0.x + pfe[rA].x + be2v.x;
            float p0B = e0.y + pfe[rB].x + be2v.x;
            p0A = (gA && p0A > 0.f) ? p0A : 0.f;
            p0B = (gB && p0B > 0.f) ? p0B : 0.f;
            *(ull*)&sPeT[(c0+0)*STRD + r0t + rA] = pk(p0A, p0B);
            float p1A = e1.x + pfe[rA].y + be2v.y;
            float p1B = e1.y + pfe[rB].y + be2v.y;
            p1A = (gA && p1A > 0.f) ? p1A : 0.f;
            p1B = (gB && p1B > 0.f) ? p1B : 0.f;
            *(ull*)&sPeT[(c0+1)*STRD + r0t + rA] = pk(p1A, p1B);
            float q0A = n0.x + pfn[rA].x + pnd.x + bn2v.x;
            float q0B = n0.y + pfn[rB].x + pnd.x + bn2v.x;
            if (gA && q0A > 0.f) np0 += q0A;
            if (gB && q0B > 0.f) np0 += q0B;
            float q1A = n1.x + pfn[rA].y + pnd.y + bn2v.y;
            float q1B = n1.y + pfn[rB].y + pnd.y + bn2v.y;
            if (gA && q1A > 0.f) np1 += q1A;
            if (gB && q1B > 0.f) np1 += q1B;
        }
        *(ull*)&sredW[ty*64 + c0] = pk(np0, np1);

        // ---- prefetch next tile (own-warp rows; LDGs fly under GEMM2) ----
        float4 pf4[4];
        if (hasn) {
            int nb = ntask >> 10, ni = ntask & 1023;
            size_t nebase = (size_t)nb*Ee + node_start(ni);
            const float4* nsrc = (const float4*)(edges + nebase*64);
            #pragma unroll
            for (int k = 0; k < 4; k++) {
                int idx = tx + 32*k;
                pf4[k] = __ldg(nsrc + (r0t + (idx >> 4))*16 + (idx & 15));
            }
        }
        __syncwarp();                        // sPeT rows are warp-local

        // ---- GEMM2: R = pair_e @ W_mean (own sPeT rows) ----
        ull acc20[4], acc21[4];
        #pragma unroll
        for (int p = 0; p < 4; p++) { acc20[p] = 0ull; acc21[p] = 0ull; }
        #pragma unroll 8
        for (int j = 0; j < 64; j++) {
            ulonglong2 aA = *(const ulonglong2*)&sPeT[j*STRD + r0t];
            ulonglong2 aB = *(const ulonglong2*)&sPeT[j*STRD + r0t + 4];
            ull a2[4] = {aA.x, aA.y, aB.x, aB.y};
            float2 wp = *(const float2*)&sW2[j*64 + c0];
            ull w20 = bcast2(wp.x);
            ull w21 = bcast2(wp.y);
            #pragma unroll
            for (int q = 0; q < 4; q++) {
                fma2(acc20[q], a2[q], w20);
                fma2(acc21[q], a2[q], w21);
            }
        }

        // ---- exclusive row-prefix (in-register) + warp totals ----
        float s0[8], s1[8];
        #pragma unroll
        for (int q = 0; q < 4; q++) {
            float2 v0 = unpk(acc20[q]);
            float2 v1 = unpk(acc21[q]);
            s0[2*q] = v0.x; s0[2*q+1] = v0.y;
            s1[2*q] = v1.x; s1[2*q+1] = v1.y;
        }
        float ex0[8], ex1[8], run0 = 0.f, run1 = 0.f;
        #pragma unroll
        for (int ri = 0; ri < 8; ri++) {
            ex0[ri] = run0; run0 += s0[ri];
            ex1[ri] = run1; run1 += s1[ri];
        }
        swrW[ty*32 + tx] = pk(run0, run1);

        // ---- store prefetched tile into alternate buffer (own rows) ----
        if (hasn) {
            #pragma unroll
            for (int k = 0; k < 4; k++) {
                int idx = tx + 32*k;
                int r = r0t + (idx >> 4), j = 4*(idx & 15);
                nxtAT[(j+0)*STRD + r] = pf4[k].x; nxtAT[(j+1)*STRD + r] = pf4[k].y;
                nxtAT[(j+2)*STRD + r] = pf4[k].z; nxtAT[(j+3)*STRD + r] = pf4[k].w;
            }
        }

        gbar(bar);                           // single group barrier: sred/swr visible

        // ---- warp-carry (predicated, unrolled) ----
        float cc0 = 0.f, cc1 = 0.f;
        #pragma unroll
        for (int t = 0; t < 7; t++) {
            if (t < ty) {
                float2 v = unpk(swrW[t*32 + tx]);
                cc0 += v.x; cc1 += v.y;
            }
        }

        // ---- out_edges: mean-scale + Q3 + bias, ReLU, float2 store ----
        {
            float2 bo2v = *(const float2*)&sbo[c0];
            #pragma unroll
            for (int q = 0; q < 4; q++) {
                float2 t0 = unpk(acc[q][4]);
                float2 t1 = unpk(acc[q][5]);
                #pragma unroll
                for (int h = 0; h < 2; h++) {
                    int ri = 2*q + h;
                    int r  = r0t + ri;
                    if (r < w) {
                        float rc = srcp[r];
                        size_t orow = (ebase + r)*64;
                        float vx = (ex0[ri] + cc0)*rc + (h ? t0.y : t0.x) + bo2v.x;
                        float vy = (ex1[ri] + cc1)*rc + (h ? t1.y : t1.x) + bo2v.y;
                        float2 o; o.x = fmaxf(vx, 0.f); o.y = fmaxf(vy, 0.f);
                        *(float2*)&out_edges[orow + c0] = o;
                    }
                }
            }
        }

        // ---- agg_n write (64 threads; no extra barrier needed) ----
        if (gtid < 64) {
            int c = gtid;
            float a = 0.f;
            #pragma unroll
            for (int t = 0; t < 8; t++) a += sredW[t*64 + c];
            g_agg[(size_t)task*64 + c] = a * (1.0f / (float)(w > 0 ? w : 1));
        }

        float* t = curAT; curAT = nxtAT; nxtAT = t;
    }
}

// ---------------- K3: out_nodes; 256 blocks x 32-row tiles ----------------
__global__ void __launch_bounds__(256,2) k_outnodes(float* __restrict__ out,
                                                    const float* __restrict__ nodes,
                                                    const float* __restrict__ W_nodes,
                                                    const float* __restrict__ bias) {
    __shared__ float sW[128*64];
    __shared__ float sA[32][132];
    __shared__ float sb[64];
    for (int idx = threadIdx.x; idx < 128*64; idx += 256) sW[idx] = W_nodes[idx];
    if (threadIdx.x < 64) sb[threadIdx.x] = bias[threadIdx.x];
    int tx = threadIdx.x & 31, ty = threadIdx.x >> 5;
    int tile = blockIdx.x;                 // 256 tiles of 32 rows
    {
        const float4* sa = (const float4*)(g_agg + (size_t)tile*32*64);
        const float4* sn = (const float4*)(nodes + (size_t)tile*32*64);
        for (int idx = threadIdx.x; idx < 32*16; idx += 256) {
            int r = idx >> 4, q = idx & 15;
            ((float4*)&sA[r][0])[q]  = sa[idx];
            ((float4*)&sA[r][64])[q] = sn[idx];
        }
    }
    __syncthreads();
    float acc[4][2];
    #pragma unroll
    for (int a = 0; a < 4; a++) { acc[a][0] = 0.f; acc[a][1] = 0.f; }
    for (int j = 0; j < 128; j += 4) {
        float4 av[4];
        #pragma unroll
        for (int ri = 0; ri < 4; ri++) av[ri] = *(const float4*)&sA[ty*4 + ri][j];
        #pragma unroll
        for (int jj = 0; jj < 4; jj++) {
            float w0 = sW[(j+jj)*64 + tx];
            float w1 = sW[(j+jj)*64 + tx + 32];
            #pragma unroll
            for (int ri = 0; ri < 4; ri++) {
                float a = (jj==0) ? av[ri].x : (jj==1) ? av[ri].y : (jj==2) ? av[ri].z : av[ri].w;
                acc[ri][0] += a * w0;
                acc[ri][1] += a * w1;
            }
        }
    }
    #pragma unroll
    for (int ri = 0; ri < 4; ri++) {
        size_t row = (size_t)tile*32 + ty*4 + ri;
        float v0 = acc[ri][0] + sb[tx];
        float v1 = acc[ri][1] + sb[tx+32];
        out[row*64 + tx]      = v0 > 0.f ? v0 : 0.f;
        out[row*64 + tx + 32] = v1 > 0.f ? v1 : 0.f;
    }
}

// ---------------- launch ----------------
extern "C" void kernel_launch(void* const* d_in, const int* in_sizes, int n_in,
                              void* d_out, int out_size) {
    const float* input_nodes = (const float*)d_in[0];
    const float* input_edges = (const float*)d_in[1];
    const float* Wn1 = (const float*)d_in[2];
    const float* bn1 = (const float*)d_in[3];
    const float* Wn2 = (const float*)d_in[4];
    const float* bn2 = (const float*)d_in[5];
    const float* We1 = (const float*)d_in[6];
    const float* be1 = (const float*)d_in[7];
    const float* We2 = (const float*)d_in[8];
    const float* be2 = (const float*)d_in[9];
    const float* W_nodes    = (const float*)d_in[10];
    const float* W_edges    = (const float*)d_in[11];
    const float* bias_edges = (const float*)d_in[12];

    float* out       = (float*)d_out;
    float* out_nodes = out;
    float* out_edges = out + (size_t)Bq*Nn*64;

    cudaFuncSetAttribute(k_fusededge, cudaFuncAttributeMaxDynamicSharedMemorySize, SMEM_BYTES);

    k_prep<<<(2*64*192 + 128 + 255)/256, 256>>>(We1, We2, be1, be2, Wn1, bn1, Wn2, bn2, W_edges);
    k_nodeproj<<<256, 256>>>(input_nodes);
    k_fusededge<<<GRID, 512, SMEM_BYTES>>>(input_edges, W_edges, bias_edges, out_edges);
    k_outnodes<<<256, 256>>>(out_nodes, input_nodes, W_nodes, bias_edges);
}

// round 16
// speedup vs baseline: 1.4142x; 1.0241x over previous
#include <cuda_runtime.h>

#define Bq 8
#define Nn 1024
#define Mw 64
#define Ee 63456
#define NROWS (Bq*Nn)          /* 8192 node rows */
#define NTASK (Bq*Nn)

#define GRID    152
#define NSTREAM (GRID*2)       /* 304 task streams */

typedef unsigned long long ull;

// ---------------- device scratch ----------------
__device__ float g_Wcat[64*192];        // edge-side:  [We_edge | Wn_edge | W_e_edge]
__device__ float g_WcatP[64*192];       // node-side:  [We_src  | Wn_src  | Wn_dst ]
__device__ float g_be[64];
__device__ float g_bn[64];
__device__ float g_P[NROWS*192];        // node projections [Pes | Pns | Pnd]
__device__ float g_agg[NROWS*64];       // agg_n

__device__ __forceinline__ int node_w(int i)      { return i < Mw ? i : Mw; }
__device__ __forceinline__ int node_start(int i)  { return i <= Mw ? (i*(i-1))/2 : 2016 + (i-Mw)*Mw; }

// ---------------- packed fp32x2 helpers ----------------
__device__ __forceinline__ void fma2(ull &d, ull a, ull b) {
    asm("fma.rn.f32x2 %0, %1, %2, %0;" : "+l"(d) : "l"(a), "l"(b));
}
__device__ __forceinline__ ull bcast2(float x) {
    ull r; asm("mov.b64 %0, {%1, %1};" : "=l"(r) : "f"(x)); return r;
}
__device__ __forceinline__ float2 unpk(ull v) {
    float2 r; asm("mov.b64 {%0, %1}, %2;" : "=f"(r.x), "=f"(r.y) : "l"(v)); return r;
}
__device__ __forceinline__ ull pk(float x, float y) {
    ull r; asm("mov.b64 %0, {%1, %2};" : "=l"(r) : "f"(x), "f"(y)); return r;
}
__device__ __forceinline__ void gbar(int id) {
    asm volatile("bar.sync %0, %1;" :: "r"(id), "r"(256) : "memory");
}
// pinned-placement vector load (volatile: ptxas cannot sink it)
__device__ __forceinline__ float2 ldg2v(const float* p) {
    float2 v;
    asm volatile("ld.global.nc.v2.f32 {%0, %1}, [%2];" : "=f"(v.x), "=f"(v.y) : "l"(p));
    return v;
}

// ---------------- shared layout (floats); tile stride 68 (16B-aligned rows) ----------------
#define STRD     68
#define SZ_AT    (64*STRD)     /* 4352 */
#define OFF_W1   0             /* 12288 */
#define OFF_W2   12288         /* 4096  */
#define OFF_BE   16384
#define OFF_BN   16448
#define OFF_BO   16512
#define OFF_RCP  16576
#define OFF_AT   16640         /* [2 grp][2 buf][4352] = 17408 */
#define OFF_PET  34048         /* [2 grp][4352] = 8704 */
#define OFF_SRED 42752         /* [2 grp][2 par][512] = 2048 */
#define OFF_SWR  44800         /* [2 grp][2 par][256 ull] = 2048 floats */
#define SMEM_FLOATS 46848
#define SMEM_BYTES  (SMEM_FLOATS*4)

// ---------------- K0: build fused weight blocks directly (EXACT R12 form) ----------------
__global__ void k_prep(const float* __restrict__ We1, const float* __restrict__ We2,
                       const float* __restrict__ be1, const float* __restrict__ be2,
                       const float* __restrict__ Wn1, const float* __restrict__ bn1,
                       const float* __restrict__ Wn2, const float* __restrict__ bn2,
                       const float* __restrict__ W_edges) {
    int idx = blockIdx.x*blockDim.x + threadIdx.x;
    if (idx < 64*192) {
        int j = idx / 192, c = idx % 192;
        float v;
        if (c < 64) {
            float s = 0.f;
            for (int t = 0; t < 128; t++) s += We1[(64+j)*128+t]*We2[t*64+c];
            v = s;
        } else if (c < 128) {
            int cc = c - 64; float s = 0.f;
            for (int t = 0; t < 128; t++) s += Wn1[(128+j)*128+t]*Wn2[t*64+cc];
            v = s;
        } else {
            v = W_edges[(64+j)*64 + (c-128)];
        }
        g_Wcat[idx] = v;
        return;
    }
    int i2 = idx - 64*192;
    if (i2 >= 0 && i2 < 64*192) {
        int j = i2 / 192, c = i2 % 192;
        float s = 0.f;
        if (c < 64) {
            for (int t = 0; t < 128; t++) s += We1[j*128+t]*We2[t*64+c];
        } else if (c < 128) {
            int cc = c - 64;
            for (int t = 0; t < 128; t++) s += Wn1[j*128+t]*Wn2[t*64+cc];
        } else {
            int cc = c - 128;
            for (int t = 0; t < 128; t++) s += Wn1[(64+j)*128+t]*Wn2[t*64+cc];
        }
        g_WcatP[i2] = s;
        return;
    }
    int i3 = idx - 2*64*192;
    if (i3 >= 0 && i3 < 64) {
        float s = be2[i3];
        for (int t = 0; t < 128; t++) s += be1[t]*We2[t*64+i3];
        g_be[i3] = s;
    } else if (i3 >= 64 && i3 < 128) {
        int c = i3 - 64; float s = bn2[c];
        for (int t = 0; t < 128; t++) s += bn1[t]*Wn2[t*64+c];
        g_bn[c] = s;
    }
}

// ---------------- K1: node projections GEMM; persistent grid-152, 32-row tiles ----------------
__global__ void __launch_bounds__(256,2) k_nodeproj(const float* __restrict__ A) {
    __shared__ float sW[64*192];
    __shared__ float sA[32][68];
    for (int idx = threadIdx.x; idx < 64*192; idx += 256) sW[idx] = g_WcatP[idx];
    int tx = threadIdx.x & 31, ty = threadIdx.x >> 5;
    const int NT = NROWS/32;               // 256 tiles of 32 rows
    for (int tile = blockIdx.x; tile < NT; tile += GRID) {
        __syncthreads();
        {
            const float4* src = (const float4*)(A + (size_t)tile*32*64);
            for (int idx = threadIdx.x; idx < 32*16; idx += 256) {
                int r = idx >> 4, q = idx & 15;
                ((float4*)&sA[r][0])[q] = src[idx];
            }
        }
        __syncthreads();
        float acc[4][6];
        #pragma unroll
        for (int a = 0; a < 4; a++)
            #pragma unroll
            for (int b = 0; b < 6; b++) acc[a][b] = 0.f;
        for (int j = 0; j < 64; j += 4) {
            float4 av[4];
            #pragma unroll
            for (int ri = 0; ri < 4; ri++) av[ri] = *(const float4*)&sA[ty*4 + ri][j];
            #pragma unroll
            for (int jj = 0; jj < 4; jj++) {
                float wv[6];
                #pragma unroll
                for (int ci = 0; ci < 6; ci++) wv[ci] = sW[(j+jj)*192 + tx + 32*ci];
                #pragma unroll
                for (int ri = 0; ri < 4; ri++) {
                    float a = (jj==0) ? av[ri].x : (jj==1) ? av[ri].y : (jj==2) ? av[ri].z : av[ri].w;
                    #pragma unroll
                    for (int ci = 0; ci < 6; ci++) acc[ri][ci] += a * wv[ci];
                }
            }
        }
        float* dst = g_P + (size_t)tile*32*192;
        #pragma unroll
        for (int ri = 0; ri < 4; ri++) {
            int r = ty*4 + ri;
            #pragma unroll
            for (int ci = 0; ci < 6; ci++)
                dst[(size_t)r*192 + tx + 32*ci] = acc[ri][ci];
        }
    }
}

// ---------------- K2: fused pipeline (EXACT R12 structure: late barrier) ----------------
__global__ void __launch_bounds__(512,1) k_fusededge(const float* __restrict__ edges,
                                                     const float* __restrict__ W_edges,
                                                     const float* __restrict__ bias,
                                                     float* __restrict__ out_edges) {
    extern __shared__ float sm[];
    float* sW1  = sm + OFF_W1;
    float* sW2  = sm + OFF_W2;
    float* sbe  = sm + OFF_BE;
    float* sbn  = sm + OFF_BN;
    float* sbo  = sm + OFF_BO;
    float* srcp = sm + OFF_RCP;
    int tid = threadIdx.x;

    for (int idx = tid; idx < 64*192; idx += 512) sW1[idx] = g_Wcat[idx];
    for (int idx = tid; idx < 64*64;  idx += 512) sW2[idx] = W_edges[idx];
    if (tid < 64) {
        sbe[tid] = g_be[tid];
        sbn[tid] = g_bn[tid];
        sbo[tid] = bias[tid];
        srcp[tid] = 1.0f / (float)(tid > 0 ? tid : 1);
    }
    __syncthreads();

    int grp  = tid >> 8;            // warp-group 0/1
    int gtid = tid & 255;
    int tx = gtid & 31, ty = gtid >> 5;
    int bar = grp + 1;
    int r0t = 8*ty;                 // this warp's first row
    int c0 = 2*tx;                  // this thread's first col per 64-segment

    float* sPeT  = sm + OFF_PET  + grp*SZ_AT;
    float* bufA  = sm + OFF_AT + (grp*2+0)*SZ_AT;
    float* bufB  = sm + OFF_AT + (grp*2+1)*SZ_AT;
    float* sredB = sm + OFF_SRED + grp*1024;
    ull*   swrB  = (ull*)(sm + OFF_SWR) + grp*512;

    int task = blockIdx.x*2 + grp;

    // ---- prologue: own-warp rows of first tile ----
    {
        int b = task >> 10, i = task & 1023;
        size_t ebase = (size_t)b*Ee + node_start(i);
        const float4* src = (const float4*)(edges + ebase*64);
        #pragma unroll
        for (int k = 0; k < 4; k++) {
            int idx = tx + 32*k;
            int rl = idx >> 4, q = idx & 15;
            float4 v = __ldg(src + (r0t + rl)*16 + q);
            int j = 4*q, r = r0t + rl;
            bufA[(j+0)*STRD + r] = v.x; bufA[(j+1)*STRD + r] = v.y;
            bufA[(j+2)*STRD + r] = v.z; bufA[(j+3)*STRD + r] = v.w;
        }
    }
    __syncwarp();

    // ---- de-phase the two warp-groups by ~half a task-round (verified) ----
    if (grp == 1) {
        long long t0 = clock64();
        while (clock64() - t0 < 8000) {}
    }

    float* curAT = bufA;
    float* nxtAT = bufB;
    int par = 0;

    for (; task < NTASK; task += NSTREAM, par ^= 1) {
        int b = task >> 10, i = task & 1023;
        int w = node_w(i), ns = node_start(i);
        size_t ebase = (size_t)b*Ee + ns;
        int srow0 = (b << 10) + (i - w);
        int ntask = task + NSTREAM;
        bool hasn = ntask < NTASK;
        float* sredW = sredB + par*512;
        ull*   swrW  = swrB + par*256;

        // ---- GEMM1 part A: j = 0..47 ----
        ull acc[4][6];
        #pragma unroll
        for (int q = 0; q < 4; q++)
            #pragma unroll
            for (int c2 = 0; c2 < 6; c2++) acc[q][c2] = 0ull;
        #pragma unroll 8
        for (int j = 0; j < 48; j++) {
            ulonglong2 aA = *(const ulonglong2*)&curAT[j*STRD + r0t];
            ulonglong2 aB = *(const ulonglong2*)&curAT[j*STRD + r0t + 4];
            ull a2[4] = {aA.x, aA.y, aB.x, aB.y};
            #pragma unroll
            for (int g = 0; g < 3; g++) {
                float2 wp = *(const float2*)&sW1[j*192 + 64*g + c0];
                ull w20 = bcast2(wp.x);
                ull w21 = bcast2(wp.y);
                #pragma unroll
                for (int q = 0; q < 4; q++) {
                    fma2(acc[q][2*g+0], a2[q], w20);
                    fma2(acc[q][2*g+1], a2[q], w21);
                }
            }
        }

        // ---- issue g_P loads NOW (covered by remaining 16 j-iters) ----
        float2 pnd, pfe[8], pfn[8];
        {
            size_t pb = (size_t)task*192;
            pnd = ldg2v(&g_P[pb + 128 + c0]);
            #pragma unroll
            for (int ri = 0; ri < 8; ri++) {
                size_t sr = (size_t)(srow0 + r0t + ri)*192;
                pfe[ri] = ldg2v(&g_P[sr + c0]);
                pfn[ri] = ldg2v(&g_P[sr + 64 + c0]);
            }
        }

        // ---- GEMM1 part B: j = 48..63 ----
        #pragma unroll 8
        for (int j = 48; j < 64; j++) {
            ulonglong2 aA = *(const ulonglong2*)&curAT[j*STRD + r0t];
            ulonglong2 aB = *(const ulonglong2*)&curAT[j*STRD + r0t + 4];
            ull a2[4] = {aA.x, aA.y, aB.x, aB.y};
            #pragma unroll
            for (int g = 0; g < 3; g++) {
                float2 wp = *(const float2*)&sW1[j*192 + 64*g + c0];
                ull w20 = bcast2(wp.x);
                ull w21 = bcast2(wp.y);
                #pragma unroll
                for (int q = 0; q < 4; q++) {
                    fma2(acc[q][2*g+0], a2[q], w20);
                    fma2(acc[q][2*g+1], a2[q], w21);
                }
            }
        }

        float2 be2v = *(const float2*)&sbe[c0];
        float2 bn2v = *(const float2*)&sbn[c0];

        // ---- epilogue: ReLU; pair_e -> sPeT (warp-local rows); pair_n partials ----
        float np0 = 0.f, np1 = 0.f;
        #pragma unroll
        for (int q = 0; q < 4; q++) {
            int rA = 2*q, rB = 2*q + 1;
            int gA = (r0t + rA) < w, gB = (r0t + rB) < w;
            float2 e0 = unpk(acc[q][0]);
            float2 e1 = unpk(acc[q][1]);
            float2 n0 = unpk(acc[q][2]);
            float2 n1 = unpk(acc[q][3]);
            float p0A = e0.x + pfe[rA].x + be2v.x;
            float p0B = e0.y + pfe[rB].x + be2v.x;
            p0A = (gA && p0A > 0.f) ? p0A : 0.f;
            p0B = (gB && p0B > 0.f) ? p0B : 0.f;
            *(ull*)&sPeT[(c0+0)*STRD + r0t + rA] = pk(p0A, p0B);
            float p1A = e1.x + pfe[rA].y + be2v.y;
            float p1B = e1.y + pfe[rB].y + be2v.y;
            p1A = (gA && p1A > 0.f) ? p1A : 0.f;
            p1B = (gB && p1B > 0.f) ? p1B : 0.f;
            *(ull*)&sPeT[(c0+1)*STRD + r0t + rA] = pk(p1A, p1B);
            float q0A = n0.x + pfn[rA].x + pnd.x + bn2v.x;
            float q0B = n0.y + pfn[rB].x + pnd.x + bn2v.x;
            if (gA && q0A > 0.f) np0 += q0A;
            if (gB && q0B > 0.f) np0 += q0B;
            float q1A = n1.x + pfn[rA].y + pnd.y + bn2v.y;
            float q1B = n1.y + pfn[rB].y + pnd.y + bn2v.y;
            if (gA && q1A > 0.f) np1 += q1A;
            if (gB && q1B > 0.f) np1 += q1B;
        }
        *(ull*)&sredW[ty*64 + c0] = pk(np0, np1);

        // ---- prefetch next tile (own-warp rows; LDGs fly under GEMM2) ----
        float4 pf4[4];
        if (hasn) {
            int nb = ntask >> 10, ni = ntask & 1023;
            size_t nebase = (size_t)nb*Ee + node_start(ni);
            const float4* nsrc = (const float4*)(edges + nebase*64);
            #pragma unroll
            for (int k = 0; k < 4; k++) {
                int idx = tx + 32*k;
                pf4[k] = __ldg(nsrc + (r0t + (idx >> 4))*16 + (idx & 15));
            }
        }
        __syncwarp();                        // sPeT rows are warp-local

        // ---- GEMM2: R = pair_e @ W_mean (own sPeT rows) ----
        ull acc20[4], acc21[4];
        #pragma unroll
        for (int p = 0; p < 4; p++) { acc20[p] = 0ull; acc21[p] = 0ull; }
        #pragma unroll 8
        for (int j = 0; j < 64; j++) {
            ulonglong2 aA = *(const ulonglong2*)&sPeT[j*STRD + r0t];
            ulonglong2 aB = *(const ulonglong2*)&sPeT[j*STRD + r0t + 4];
            ull a2[4] = {aA.x, aA.y, aB.x, aB.y};
            float2 wp = *(const float2*)&sW2[j*64 + c0];
            ull w20 = bcast2(wp.x);
            ull w21 = bcast2(wp.y);
            #pragma unroll
            for (int q = 0; q < 4; q++) {
                fma2(acc20[q], a2[q], w20);
                fma2(acc21[q], a2[q], w21);
            }
        }

        // ---- exclusive row-prefix (in-register) + warp totals ----
        float s0[8], s1[8];
        #pragma unroll
        for (int q = 0; q < 4; q++) {
            float2 v0 = unpk(acc20[q]);
            float2 v1 = unpk(acc21[q]);
            s0[2*q] = v0.x; s0[2*q+1] = v0.y;
            s1[2*q] = v1.x; s1[2*q+1] = v1.y;
        }
        float ex0[8], ex1[8], run0 = 0.f, run1 = 0.f;
        #pragma unroll
        for (int ri = 0; ri < 8; ri++) {
            ex0[ri] = run0; run0 += s0[ri];
            ex1[ri] = run1; run1 += s1[ri];
        }
        swrW[ty*32 + tx] = pk(run0, run1);

        // ---- store prefetched tile into alternate buffer (own rows) ----
        if (hasn) {
            #pragma unroll
            for (int k = 0; k < 4; k++) {
                int idx = tx + 32*k;
                int r = r0t + (idx >> 4), j = 4*(idx & 15);
                nxtAT[(j+0)*STRD + r] = pf4[k].x; nxtAT[(j+1)*STRD + r] = pf4[k].y;
                nxtAT[(j+2)*STRD + r] = pf4[k].z; nxtAT[(j+3)*STRD + r] = pf4[k].w;
            }
        }

        gbar(bar);                           // single group barrier: sred/swr visible

        // ---- warp-carry (predicated, unrolled) ----
        float cc0 = 0.f, cc1 = 0.f;
        #pragma unroll
        for (int t = 0; t < 7; t++) {
            if (t < ty) {
                float2 v = unpk(swrW[t*32 + tx]);
                cc0 += v.x; cc1 += v.y;
            }
        }

        // ---- out_edges: mean-scale + Q3 + bias, ReLU, float2 store ----
        {
            float2 bo2v = *(const float2*)&sbo[c0];
            #pragma unroll
            for (int q = 0; q < 4; q++) {
                float2 t0 = unpk(acc[q][4]);
                float2 t1 = unpk(acc[q][5]);
                #pragma unroll
                for (int h = 0; h < 2; h++) {
                    int ri = 2*q + h;
                    int r  = r0t + ri;
                    if (r < w) {
                        float rc = srcp[r];
                        size_t orow = (ebase + r)*64;
                        float vx = (ex0[ri] + cc0)*rc + (h ? t0.y : t0.x) + bo2v.x;
                        float vy = (ex1[ri] + cc1)*rc + (h ? t1.y : t1.x) + bo2v.y;
                        float2 o; o.x = fmaxf(vx, 0.f); o.y = fmaxf(vy, 0.f);
                        *(float2*)&out_edges[orow + c0] = o;
                    }
                }
            }
        }

        // ---- agg_n write (64 threads; no extra barrier needed) ----
        if (gtid < 64) {
            int c = gtid;
            float a = 0.f;
            #pragma unroll
            for (int t = 0; t < 8; t++) a += sredW[t*64 + c];
            g_agg[(size_t)task*64 + c] = a * (1.0f / (float)(w > 0 ? w : 1));
        }

        float* t = curAT; curAT = nxtAT; nxtAT = t;
    }
}

// ---------------- K3: out_nodes; persistent grid-152, 32-row tiles ----------------
__global__ void __launch_bounds__(256,2) k_outnodes(float* __restrict__ out,
                                                    const float* __restrict__ nodes,
                                                    const float* __restrict__ W_nodes,
                                                    const float* __restrict__ bias) {
    __shared__ float sW[128*64];
    __shared__ float sA[32][132];
    __shared__ float sb[64];
    for (int idx = threadIdx.x; idx < 128*64; idx += 256) sW[idx] = W_nodes[idx];
    if (threadIdx.x < 64) sb[threadIdx.x] = bias[threadIdx.x];
    int tx = threadIdx.x & 31, ty = threadIdx.x >> 5;
    const int NT = NROWS/32;               // 256 tiles of 32 rows
    for (int tile = blockIdx.x; tile < NT; tile += GRID) {
        __syncthreads();
        {
            const float4* sa = (const float4*)(g_agg + (size_t)tile*32*64);
            const float4* sn = (const float4*)(nodes + (size_t)tile*32*64);
            for (int idx = threadIdx.x; idx < 32*16; idx += 256) {
                int r = idx >> 4, q = idx & 15;
                ((float4*)&sA[r][0])[q]  = sa[idx];
                ((float4*)&sA[r][64])[q] = sn[idx];
            }
        }
        __syncthreads();
        float acc[4][2];
        #pragma unroll
        for (int a = 0; a < 4; a++) { acc[a][0] = 0.f; acc[a][1] = 0.f; }
        for (int j = 0; j < 128; j += 4) {
            float4 av[4];
            #pragma unroll
            for (int ri = 0; ri < 4; ri++) av[ri] = *(const float4*)&sA[ty*4 + ri][j];
            #pragma unroll
            for (int jj = 0; jj < 4; jj++) {
                float w0 = sW[(j+jj)*64 + tx];
                float w1 = sW[(j+jj)*64 + tx + 32];
                #pragma unroll
                for (int ri = 0; ri < 4; ri++) {
                    float a = (jj==0) ? av[ri].x : (jj==1) ? av[ri].y : (jj==2) ? av[ri].z : av[ri].w;
                    acc[ri][0] += a * w0;
                    acc[ri][1] += a * w1;
                }
            }
        }
        #pragma unroll
        for (int ri = 0; ri < 4; ri++) {
            size_t row = (size_t)tile*32 + ty*4 + ri;
            float v0 = acc[ri][0] + sb[tx];
            float v1 = acc[ri][1] + sb[tx+32];
            out[row*64 + tx]      = v0 > 0.f ? v0 : 0.f;
            out[row*64 + tx + 32] = v1 > 0.f ? v1 : 0.f;
        }
    }
}

// ---------------- launch ----------------
extern "C" void kernel_launch(void* const* d_in, const int* in_sizes, int n_in,
                              void* d_out, int out_size) {
    const float* input_nodes = (const float*)d_in[0];
    const float* input_edges = (const float*)d_in[1];
    const float* Wn1 = (const float*)d_in[2];
    const float* bn1 = (const float*)d_in[3];
    const float* Wn2 = (const float*)d_in[4];
    const float* bn2 = (const float*)d_in[5];
    const float* We1 = (const float*)d_in[6];
    const float* be1 = (const float*)d_in[7];
    const float* We2 = (const float*)d_in[8];
    const float* be2 = (const float*)d_in[9];
    const float* W_nodes    = (const float*)d_in[10];
    const float* W_edges    = (const float*)d_in[11];
    const float* bias_edges = (const float*)d_in[12];

    float* out       = (float*)d_out;
    float* out_nodes = out;
    float* out_edges = out + (size_t)Bq*Nn*64;

    cudaFuncSetAttribute(k_fusededge, cudaFuncAttributeMaxDynamicSharedMemorySize, SMEM_BYTES);

    k_prep<<<(2*64*192 + 128 + 255)/256, 256>>>(We1, We2, be1, be2, Wn1, bn1, Wn2, bn2, W_edges);
    k_nodeproj<<<GRID, 256>>>(input_nodes);
    k_fusededge<<<GRID, 512, SMEM_BYTES>>>(input_edges, W_edges, bias_edges, out_edges);
    k_outnodes<<<GRID, 256>>>(out_nodes, input_nodes, W_nodes, bias_edges);
}

// round 17
// speedup vs baseline: 1.4296x; 1.0109x over previous
#include <cuda_runtime.h>

#define Bq 8
#define Nn 1024
#define Mw 64
#define Ee 63456
#define NROWS (Bq*Nn)          /* 8192 node rows */
#define NTASK (Bq*Nn)

#define GRID    152
#define NSTREAM (GRID*2)       /* 304 task streams */

typedef unsigned long long ull;

// ---------------- device scratch ----------------
__device__ float g_Wcat[64*192];        // edge-side:  [We_edge | Wn_edge | W_e_edge]
__device__ float g_WcatP[64*192];       // node-side:  [We_src  | Wn_src  | Wn_dst ]
__device__ float g_be[64];
__device__ float g_bn[64];
__device__ float g_P[NROWS*192];        // node projections [Pes | Pns | Pnd]
__device__ float g_agg[NROWS*64];       // agg_n

__device__ __forceinline__ int node_w(int i)      { return i < Mw ? i : Mw; }
__device__ __forceinline__ int node_start(int i)  { return i <= Mw ? (i*(i-1))/2 : 2016 + (i-Mw)*Mw; }

// ---------------- packed fp32x2 helpers ----------------
__device__ __forceinline__ void fma2(ull &d, ull a, ull b) {
    asm("fma.rn.f32x2 %0, %1, %2, %0;" : "+l"(d) : "l"(a), "l"(b));
}
__device__ __forceinline__ ull bcast2(float x) {
    ull r; asm("mov.b64 %0, {%1, %1};" : "=l"(r) : "f"(x)); return r;
}
__device__ __forceinline__ float2 unpk(ull v) {
    float2 r; asm("mov.b64 {%0, %1}, %2;" : "=f"(r.x), "=f"(r.y) : "l"(v)); return r;
}
__device__ __forceinline__ ull pk(float x, float y) {
    ull r; asm("mov.b64 %0, {%1, %2};" : "=l"(r) : "f"(x), "f"(y)); return r;
}
__device__ __forceinline__ void gbar(int id) {
    asm volatile("bar.sync %0, %1;" :: "r"(id), "r"(256) : "memory");
}
// pinned-placement vector load (volatile: ptxas cannot sink it)
__device__ __forceinline__ float2 ldg2v(const float* p) {
    float2 v;
    asm volatile("ld.global.nc.v2.f32 {%0, %1}, [%2];" : "=f"(v.x), "=f"(v.y) : "l"(p));
    return v;
}

// ---------------- shared layout (floats); tile stride 68 (16B-aligned rows) ----------------
#define STRD     68
#define SZ_AT    (64*STRD)     /* 4352 */
#define OFF_W1   0             /* 12288 */
#define OFF_W2   12288         /* 4096  */
#define OFF_BE   16384
#define OFF_BN   16448
#define OFF_BO   16512
#define OFF_RCP  16576
#define OFF_AT   16640         /* [2 grp][2 buf][4352] = 17408 */
#define OFF_PET  34048         /* [2 grp][4352] = 8704 */
#define OFF_SRED 42752         /* [2 grp][2 par][512] = 2048 */
#define OFF_SWR  44800         /* [2 grp][2 par][256 ull] = 2048 floats */
#define SMEM_FLOATS 46848
#define SMEM_BYTES  (SMEM_FLOATS*4)

// ---------------- K0: build fused weight blocks directly ----------------
__global__ void k_prep(const float* __restrict__ We1, const float* __restrict__ We2,
                       const float* __restrict__ be1, const float* __restrict__ be2,
                       const float* __restrict__ Wn1, const float* __restrict__ bn1,
                       const float* __restrict__ Wn2, const float* __restrict__ bn2,
                       const float* __restrict__ W_edges) {
    int idx = blockIdx.x*blockDim.x + threadIdx.x;
    if (idx < 64*192) {
        int j = idx / 192, c = idx % 192;
        float v;
        if (c < 64) {
            float s = 0.f;
            for (int t = 0; t < 128; t++) s += We1[(64+j)*128+t]*We2[t*64+c];
            v = s;
        } else if (c < 128) {
            int cc = c - 64; float s = 0.f;
            for (int t = 0; t < 128; t++) s += Wn1[(128+j)*128+t]*Wn2[t*64+cc];
            v = s;
        } else {
            v = W_edges[(64+j)*64 + (c-128)];
        }
        g_Wcat[idx] = v;
        return;
    }
    int i2 = idx - 64*192;
    if (i2 >= 0 && i2 < 64*192) {
        int j = i2 / 192, c = i2 % 192;
        float s = 0.f;
        if (c < 64) {
            for (int t = 0; t < 128; t++) s += We1[j*128+t]*We2[t*64+c];
        } else if (c < 128) {
            int cc = c - 64;
            for (int t = 0; t < 128; t++) s += Wn1[j*128+t]*Wn2[t*64+cc];
        } else {
            int cc = c - 128;
            for (int t = 0; t < 128; t++) s += Wn1[(64+j)*128+t]*Wn2[t*64+cc];
        }
        g_WcatP[i2] = s;
        return;
    }
    int i3 = idx - 2*64*192;
    if (i3 >= 0 && i3 < 64) {
        float s = be2[i3];
        for (int t = 0; t < 128; t++) s += be1[t]*We2[t*64+i3];
        g_be[i3] = s;
    } else if (i3 >= 64 && i3 < 128) {
        int c = i3 - 64; float s = bn2[c];
        for (int t = 0; t < 128; t++) s += bn1[t]*Wn2[t*64+c];
        g_bn[c] = s;
    }
}

// ---------------- K1: node projections GEMM; 256 blocks x 32-row tiles ----------------
__global__ void __launch_bounds__(256,2) k_nodeproj(const float* __restrict__ A) {
    __shared__ float sW[64*192];
    __shared__ float sA[32][68];
    for (int idx = threadIdx.x; idx < 64*192; idx += 256) sW[idx] = g_WcatP[idx];
    int tx = threadIdx.x & 31, ty = threadIdx.x >> 5;
    int tile = blockIdx.x;                 // 256 tiles of 32 rows
    {
        const float4* src = (const float4*)(A + (size_t)tile*32*64);
        for (int idx = threadIdx.x; idx < 32*16; idx += 256) {
            int r = idx >> 4, q = idx & 15;
            ((float4*)&sA[r][0])[q] = src[idx];
        }
    }
    __syncthreads();
    float acc[4][6];
    #pragma unroll
    for (int a = 0; a < 4; a++)
        #pragma unroll
        for (int b = 0; b < 6; b++) acc[a][b] = 0.f;
    for (int j = 0; j < 64; j += 4) {
        float4 av[4];
        #pragma unroll
        for (int ri = 0; ri < 4; ri++) av[ri] = *(const float4*)&sA[ty*4 + ri][j];
        #pragma unroll
        for (int jj = 0; jj < 4; jj++) {
            float wv[6];
            #pragma unroll
            for (int ci = 0; ci < 6; ci++) wv[ci] = sW[(j+jj)*192 + tx + 32*ci];
            #pragma unroll
            for (int ri = 0; ri < 4; ri++) {
                float a = (jj==0) ? av[ri].x : (jj==1) ? av[ri].y : (jj==2) ? av[ri].z : av[ri].w;
                #pragma unroll
                for (int ci = 0; ci < 6; ci++) acc[ri][ci] += a * wv[ci];
            }
        }
    }
    float* dst = g_P + (size_t)tile*32*192;
    #pragma unroll
    for (int ri = 0; ri < 4; ri++) {
        int r = ty*4 + ri;
        #pragma unroll
        for (int ci = 0; ci < 6; ci++)
            dst[(size_t)r*192 + tx + 32*ci] = acc[ri][ci];
    }
}

// ---------------- K2: fused pipeline (R12: late barrier, de-phase, split prefetch) ----------------
__global__ void __launch_bounds__(512,1) k_fusededge(const float* __restrict__ edges,
                                                     const float* __restrict__ W_edges,
                                                     const float* __restrict__ bias,
                                                     float* __restrict__ out_edges) {
    extern __shared__ float sm[];
    float* sW1  = sm + OFF_W1;
    float* sW2  = sm + OFF_W2;
    float* sbe  = sm + OFF_BE;
    float* sbn  = sm + OFF_BN;
    float* sbo  = sm + OFF_BO;
    float* srcp = sm + OFF_RCP;
    int tid = threadIdx.x;

    for (int idx = tid; idx < 64*192; idx += 512) sW1[idx] = g_Wcat[idx];
    for (int idx = tid; idx < 64*64;  idx += 512) sW2[idx] = W_edges[idx];
    if (tid < 64) {
        sbe[tid] = g_be[tid];
        sbn[tid] = g_bn[tid];
        sbo[tid] = bias[tid];
        srcp[tid] = 1.0f / (float)(tid > 0 ? tid : 1);
    }
    __syncthreads();

    int grp  = tid >> 8;            // warp-group 0/1
    int gtid = tid & 255;
    int tx = gtid & 31, ty = gtid >> 5;
    int bar = grp + 1;
    int r0t = 8*ty;                 // this warp's first row
    int c0 = 2*tx;                  // this thread's first col per 64-segment

    float* sPeT  = sm + OFF_PET  + grp*SZ_AT;
    float* bufA  = sm + OFF_AT + (grp*2+0)*SZ_AT;
    float* bufB  = sm + OFF_AT + (grp*2+1)*SZ_AT;
    float* sredB = sm + OFF_SRED + grp*1024;
    ull*   swrB  = (ull*)(sm + OFF_SWR) + grp*512;

    int task = blockIdx.x*2 + grp;

    // ---- prologue: own-warp rows of first tile ----
    {
        int b = task >> 10, i = task & 1023;
        size_t ebase = (size_t)b*Ee + node_start(i);
        const float4* src = (const float4*)(edges + ebase*64);
        #pragma unroll
        for (int k = 0; k < 4; k++) {
            int idx = tx + 32*k;
            int rl = idx >> 4, q = idx & 15;
            float4 v = __ldg(src + (r0t + rl)*16 + q);
            int j = 4*q, r = r0t + rl;
            bufA[(j+0)*STRD + r] = v.x; bufA[(j+1)*STRD + r] = v.y;
            bufA[(j+2)*STRD + r] = v.z; bufA[(j+3)*STRD + r] = v.w;
        }
    }
    __syncwarp();

    // ---- de-phase the two warp-groups by ~half a task-round (verified) ----
    if (grp == 1) {
        long long t0 = clock64();
        while (clock64() - t0 < 8000) {}
    }

    float* curAT = bufA;
    float* nxtAT = bufB;
    int par = 0;

    for (; task < NTASK; task += NSTREAM, par ^= 1) {
        int b = task >> 10, i = task & 1023;
        int w = node_w(i), ns = node_start(i);
        size_t ebase = (size_t)b*Ee + ns;
        int srow0 = (b << 10) + (i - w);
        int ntask = task + NSTREAM;
        bool hasn = ntask < NTASK;
        float* sredW = sredB + par*512;
        ull*   swrW  = swrB + par*256;

        // ---- GEMM1 part A: j = 0..47 ----
        ull acc[4][6];
        #pragma unroll
        for (int q = 0; q < 4; q++)
            #pragma unroll
            for (int c2 = 0; c2 < 6; c2++) acc[q][c2] = 0ull;
        #pragma unroll 8
        for (int j = 0; j < 48; j++) {
            ulonglong2 aA = *(const ulonglong2*)&curAT[j*STRD + r0t];
            ulonglong2 aB = *(const ulonglong2*)&curAT[j*STRD + r0t + 4];
            ull a2[4] = {aA.x, aA.y, aB.x, aB.y};
            #pragma unroll
            for (int g = 0; g < 3; g++) {
                float2 wp = *(const float2*)&sW1[j*192 + 64*g + c0];
                ull w20 = bcast2(wp.x);
                ull w21 = bcast2(wp.y);
                #pragma unroll
                for (int q = 0; q < 4; q++) {
                    fma2(acc[q][2*g+0], a2[q], w20);
                    fma2(acc[q][2*g+1], a2[q], w21);
                }
            }
        }

        // ---- issue g_P loads NOW (covered by remaining 16 j-iters) ----
        float2 pnd, pfe[8], pfn[8];
        {
            size_t pb = (size_t)task*192;
            pnd = ldg2v(&g_P[pb + 128 + c0]);
            #pragma unroll
            for (int ri = 0; ri < 8; ri++) {
                size_t sr = (size_t)(srow0 + r0t + ri)*192;
                pfe[ri] = ldg2v(&g_P[sr + c0]);
                pfn[ri] = ldg2v(&g_P[sr + 64 + c0]);
            }
        }

        // ---- GEMM1 part B: j = 48..63 ----
        #pragma unroll 8
        for (int j = 48; j < 64; j++) {
            ulonglong2 aA = *(const ulonglong2*)&curAT[j*STRD + r0t];
            ulonglong2 aB = *(const ulonglong2*)&curAT[j*STRD + r0t + 4];
            ull a2[4] = {aA.x, aA.y, aB.x, aB.y};
            #pragma unroll
            for (int g = 0; g < 3; g++) {
                float2 wp = *(const float2*)&sW1[j*192 + 64*g + c0];
                ull w20 = bcast2(wp.x);
                ull w21 = bcast2(wp.y);
                #pragma unroll
                for (int q = 0; q < 4; q++) {
                    fma2(acc[q][2*g+0], a2[q], w20);
                    fma2(acc[q][2*g+1], a2[q], w21);
                }
            }
        }

        float2 be2v = *(const float2*)&sbe[c0];
        float2 bn2v = *(const float2*)&sbn[c0];

        // ---- epilogue: ReLU; pair_e -> sPeT (warp-local rows); pair_n partials ----
        float np0 = 0.f, np1 = 0.f;
        #pragma unroll
        for (int q = 0; q < 4; q++) {
            int rA = 2*q, rB = 2*q + 1;
            int gA = (r0t + rA) < w, gB = (r0t + rB) < w;
            float2 e0 = unpk(acc[q][0]);
            float2 e1 = unpk(acc[q][1]);
            float2 n0 = unpk(acc[q][2]);
            float2 n1 = unpk(acc[q][3]);
            float p0A = e0.x + pfe[rA].x + be2v.x;
            float p0B = e0.y + pfe[rB].x + be2v.x;
            p0A = (gA && p0A > 0.f) ? p0A : 0.f;
            p0B = (gB && p0B > 0.f) ? p0B : 0.f;
            *(ull*)&sPeT[(c0+0)*STRD + r0t + rA] = pk(p0A, p0B);
            float p1A = e1.x + pfe[rA].y + be2v.y;
            float p1B = e1.y + pfe[rB].y + be2v.y;
            p1A = (gA && p1A > 0.f) ? p1A : 0.f;
            p1B = (gB && p1B > 0.f) ? p1B : 0.f;
            *(ull*)&sPeT[(c0+1)*STRD + r0t + rA] = pk(p1A, p1B);
            float q0A = n0.x + pfn[rA].x + pnd.x + bn2v.x;
            float q0B = n0.y + pfn[rB].x + pnd.x + bn2v.x;
            if (gA && q0A > 0.f) np0 += q0A;
            if (gB && q0B > 0.f) np0 += q0B;
            float q1A = n1.x + pfn[rA].y + pnd.y + bn2v.y;
            float q1B = n1.y + pfn[rB].y + pnd.y + bn2v.y;
            if (gA && q1A > 0.f) np1 += q1A;
            if (gB && q1B > 0.f) np1 += q1B;
        }
        *(ull*)&sredW[ty*64 + c0] = pk(np0, np1);

        // ---- prefetch next tile (own-warp rows; LDGs fly under GEMM2) ----
        float4 pf4[4];
        if (hasn) {
            int nb = ntask >> 10, ni = ntask & 1023;
            size_t nebase = (size_t)nb*Ee + node_start(ni);
            const float4* nsrc = (const float4*)(edges + nebase*64);
            #pragma unroll
            for (int k = 0; k < 4; k++) {
                int idx = tx + 32*k;
                pf4[k] = __ldg(nsrc + (r0t + (idx >> 4))*16 + (idx & 15));
            }
        }
        __syncwarp();                        // sPeT rows are warp-local

        // ---- GEMM2: R = pair_e @ W_mean (own sPeT rows) ----
        ull acc20[4], acc21[4];
        #pragma unroll
        for (int p = 0; p < 4; p++) { acc20[p] = 0ull; acc21[p] = 0ull; }
        #pragma unroll 8
        for (int j = 0; j < 64; j++) {
            ulonglong2 aA = *(const ulonglong2*)&sPeT[j*STRD + r0t];
            ulonglong2 aB = *(const ulonglong2*)&sPeT[j*STRD + r0t + 4];
            ull a2[4] = {aA.x, aA.y, aB.x, aB.y};
            float2 wp = *(const float2*)&sW2[j*64 + c0];
            ull w20 = bcast2(wp.x);
            ull w21 = bcast2(wp.y);
            #pragma unroll
            for (int q = 0; q < 4; q++) {
                fma2(acc20[q], a2[q], w20);
                fma2(acc21[q], a2[q], w21);
            }
        }

        // ---- exclusive row-prefix (in-register) + warp totals ----
        float s0[8], s1[8];
        #pragma unroll
        for (int q = 0; q < 4; q++) {
            float2 v0 = unpk(acc20[q]);
            float2 v1 = unpk(acc21[q]);
            s0[2*q] = v0.x; s0[2*q+1] = v0.y;
            s1[2*q] = v1.x; s1[2*q+1] = v1.y;
        }
        float ex0[8], ex1[8], run0 = 0.f, run1 = 0.f;
        #pragma unroll
        for (int ri = 0; ri < 8; ri++) {
            ex0[ri] = run0; run0 += s0[ri];
            ex1[ri] = run1; run1 += s1[ri];
        }
        swrW[ty*32 + tx] = pk(run0, run1);

        // ---- store prefetched tile into alternate buffer (own rows) ----
        if (hasn) {
            #pragma unroll
            for (int k = 0; k < 4; k++) {
                int idx = tx + 32*k;
                int r = r0t + (idx >> 4), j = 4*(idx & 15);
                nxtAT[(j+0)*STRD + r] = pf4[k].x; nxtAT[(j+1)*STRD + r] = pf4[k].y;
                nxtAT[(j+2)*STRD + r] = pf4[k].z; nxtAT[(j+3)*STRD + r] = pf4[k].w;
            }
        }

        gbar(bar);                           // single group barrier: sred/swr visible

        // ---- warp-carry (predicated, unrolled) ----
        float cc0 = 0.f, cc1 = 0.f;
        #pragma unroll
        for (int t = 0; t < 7; t++) {
            if (t < ty) {
                float2 v = unpk(swrW[t*32 + tx]);
                cc0 += v.x; cc1 += v.y;
            }
        }

        // ---- out_edges: mean-scale + Q3 + bias, ReLU, float2 store ----
        {
            float2 bo2v = *(const float2*)&sbo[c0];
            #pragma unroll
            for (int q = 0; q < 4; q++) {
                float2 t0 = unpk(acc[q][4]);
                float2 t1 = unpk(acc[q][5]);
                #pragma unroll
                for (int h = 0; h < 2; h++) {
                    int ri = 2*q + h;
                    int r  = r0t + ri;
                    if (r < w) {
                        float rc = srcp[r];
                        size_t orow = (ebase + r)*64;
                        float vx = (ex0[ri] + cc0)*rc + (h ? t0.y : t0.x) + bo2v.x;
                        float vy = (ex1[ri] + cc1)*rc + (h ? t1.y : t1.x) + bo2v.y;
                        float2 o; o.x = fmaxf(vx, 0.f); o.y = fmaxf(vy, 0.f);
                        *(float2*)&out_edges[orow + c0] = o;
                    }
                }
            }
        }

        // ---- agg_n write (64 threads; no extra barrier needed) ----
        if (gtid < 64) {
            int c = gtid;
            float a = 0.f;
            #pragma unroll
            for (int t = 0; t < 8; t++) a += sredW[t*64 + c];
            g_agg[(size_t)task*64 + c] = a * (1.0f / (float)(w > 0 ? w : 1));
        }

        float* t = curAT; curAT = nxtAT; nxtAT = t;
    }
}

// ---------------- K3: out_nodes; 256 blocks x 32-row tiles ----------------
__global__ void __launch_bounds__(256,2) k_outnodes(float* __restrict__ out,
                                                    const float* __restrict__ nodes,
                                                    const float* __restrict__ W_nodes,
                                                    const float* __restrict__ bias) {
    __shared__ float sW[128*64];
    __shared__ float sA[32][132];
    __shared__ float sb[64];
    for (int idx = threadIdx.x; idx < 128*64; idx += 256) sW[idx] = W_nodes[idx];
    if (threadIdx.x < 64) sb[threadIdx.x] = bias[threadIdx.x];
    int tx = threadIdx.x & 31, ty = threadIdx.x >> 5;
    int tile = blockIdx.x;                 // 256 tiles of 32 rows
    {
        const float4* sa = (const float4*)(g_agg + (size_t)tile*32*64);
        const float4* sn = (const float4*)(nodes + (size_t)tile*32*64);
        for (int idx = threadIdx.x; idx < 32*16; idx += 256) {
            int r = idx >> 4, q = idx & 15;
            ((float4*)&sA[r][0])[q]  = sa[idx];
            ((float4*)&sA[r][64])[q] = sn[idx];
        }
    }
    __syncthreads();
    float acc[4][2];
    #pragma unroll
    for (int a = 0; a < 4; a++) { acc[a][0] = 0.f; acc[a][1] = 0.f; }
    for (int j = 0; j < 128; j += 4) {
        float4 av[4];
        #pragma unroll
        for (int ri = 0; ri < 4; ri++) av[ri] = *(const float4*)&sA[ty*4 + ri][j];
        #pragma unroll
        for (int jj = 0; jj < 4; jj++) {
            float w0 = sW[(j+jj)*64 + tx];
            float w1 = sW[(j+jj)*64 + tx + 32];
            #pragma unroll
            for (int ri = 0; ri < 4; ri++) {
                float a = (jj==0) ? av[ri].x : (jj==1) ? av[ri].y : (jj==2) ? av[ri].z : av[ri].w;
                acc[ri][0] += a * w0;
                acc[ri][1] += a * w1;
            }
        }
    }
    #pragma unroll
    for (int ri = 0; ri < 4; ri++) {
        size_t row = (size_t)tile*32 + ty*4 + ri;
        float v0 = acc[ri][0] + sb[tx];
        float v1 = acc[ri][1] + sb[tx+32];
        out[row*64 + tx]      = v0 > 0.f ? v0 : 0.f;
        out[row*64 + tx + 32] = v1 > 0.f ? v1 : 0.f;
    }
}

// ---------------- launch ----------------
extern "C" void kernel_launch(void* const* d_in, const int* in_sizes, int n_in,
                              void* d_out, int out_size) {
    const float* input_nodes = (const float*)d_in[0];
    const float* input_edges = (const float*)d_in[1];
    const float* Wn1 = (const float*)d_in[2];
    const float* bn1 = (const float*)d_in[3];
    const float* Wn2 = (const float*)d_in[4];
    const float* bn2 = (const float*)d_in[5];
    const float* We1 = (const float*)d_in[6];
    const float* be1 = (const float*)d_in[7];
    const float* We2 = (const float*)d_in[8];
    const float* be2 = (const float*)d_in[9];
    const float* W_nodes    = (const float*)d_in[10];
    const float* W_edges    = (const float*)d_in[11];
    const float* bias_edges = (const float*)d_in[12];

    float* out       = (float*)d_out;
    float* out_nodes = out;
    float* out_edges = out + (size_t)Bq*Nn*64;

    cudaFuncSetAttribute(k_fusededge, cudaFuncAttributeMaxDynamicSharedMemorySize, SMEM_BYTES);

    k_prep<<<(2*64*192 + 128 + 255)/256, 256>>>(We1, We2, be1, be2, Wn1, bn1, Wn2, bn2, W_edges);
    k_nodeproj<<<256, 256>>>(input_nodes);
    k_fusededge<<<GRID, 512, SMEM_BYTES>>>(input_edges, W_edges, bias_edges, out_edges);
    k_outnodes<<<256, 256>>>(out_nodes, input_nodes, W_nodes, bias_edges);
}